// round 2
// baseline (speedup 1.0000x reference)
#include <cuda_runtime.h>
#include <cuda_bf16.h>

#define B_ 4
#define S_ 2048
#define H_ 8
#define D_ 64
#define DM_ 512

typedef unsigned long long ull;

// ---------------- device scratch (no cudaMalloc allowed) ----------------
__device__ float g_qt[B_ * H_ * D_ * S_];      // [B*H][D][S]  (transposed)
__device__ float g_kt[B_ * H_ * D_ * S_];      // [B*H][D][S]  (transposed)
__device__ float g_v [B_ * H_ * S_ * D_];      // [B*H][S][D]
__device__ float g_bias[(size_t)B_ * S_ * S_]; // [B][S][S] gathered gene bias
__device__ float g_ctx[B_ * S_ * DM_];         // [B][S][DM] attention output

// ---------------- f32x2 packed helpers ----------------
__device__ __forceinline__ ull pack2(float x, float y) {
    ull r; asm("mov.b64 %0, {%1,%2};" : "=l"(r) : "f"(x), "f"(y)); return r;
}
__device__ __forceinline__ ull fma2(ull a, ull b, ull c) {
    ull d; asm("fma.rn.f32x2 %0, %1, %2, %3;" : "=l"(d) : "l"(a), "l"(b), "l"(c)); return d;
}
__device__ __forceinline__ ull mul2(ull a, ull b) {
    ull d; asm("mul.rn.f32x2 %0, %1, %2;" : "=l"(d) : "l"(a), "l"(b)); return d;
}
__device__ __forceinline__ void unpack2(ull p, float& x, float& y) {
    asm("mov.b64 {%0,%1}, %2;" : "=f"(x), "=f"(y) : "l"(p));
}

// ============================================================
// Kernel 1: QKV projection.  qkv[m][n] = sum_k A[m][k]*W[n][k] + bias[n]
// M=8192 (B*S), N=1536, K=512.  128x128 tile, BK=16, 256 threads,
// 8x8 microtile with f32x2 row-pair accumulators.
// Q and K are written TRANSPOSED ([bh][d][s]); V normal ([bh][s][d]).
// ============================================================
__global__ __launch_bounds__(256) void qkv_gemm_kernel(
    const float* __restrict__ A, const float* __restrict__ W,
    const float* __restrict__ bias)
{
    __shared__ __align__(16) float As[16][128];
    __shared__ __align__(16) float Bs[16][128];
    const int bm = blockIdx.y * 128;
    const int bn = blockIdx.x * 128;
    const int tid = threadIdx.x;
    const int tx = tid & 15, ty = tid >> 4;
    const int lr = tid >> 2;
    const int lc = (tid & 3) << 2;

    ull acc2[4][8];
#pragma unroll
    for (int i = 0; i < 4; i++)
#pragma unroll
        for (int j = 0; j < 8; j++) acc2[i][j] = 0ull;

    for (int kt = 0; kt < 512; kt += 16) {
        float4 a0 = *(const float4*)&A[(size_t)(bm + lr) * 512 + kt + lc];
        float4 a1 = *(const float4*)&A[(size_t)(bm + lr + 64) * 512 + kt + lc];
        float4 b0 = *(const float4*)&W[(size_t)(bn + lr) * 512 + kt + lc];
        float4 b1 = *(const float4*)&W[(size_t)(bn + lr + 64) * 512 + kt + lc];
        As[lc + 0][lr] = a0.x; As[lc + 1][lr] = a0.y; As[lc + 2][lr] = a0.z; As[lc + 3][lr] = a0.w;
        As[lc + 0][lr + 64] = a1.x; As[lc + 1][lr + 64] = a1.y; As[lc + 2][lr + 64] = a1.z; As[lc + 3][lr + 64] = a1.w;
        Bs[lc + 0][lr] = b0.x; Bs[lc + 1][lr] = b0.y; Bs[lc + 2][lr] = b0.z; Bs[lc + 3][lr] = b0.w;
        Bs[lc + 0][lr + 64] = b1.x; Bs[lc + 1][lr + 64] = b1.y; Bs[lc + 2][lr + 64] = b1.z; Bs[lc + 3][lr + 64] = b1.w;
        __syncthreads();
#pragma unroll
        for (int kk = 0; kk < 16; kk++) {
            const ull* ap = (const ull*)&As[kk][ty * 8];
            ull a[4] = {ap[0], ap[1], ap[2], ap[3]};
            float4 bv0 = ((const float4*)Bs[kk])[tx * 2];
            float4 bv1 = ((const float4*)Bs[kk])[tx * 2 + 1];
            ull bd[8] = {pack2(bv0.x, bv0.x), pack2(bv0.y, bv0.y),
                         pack2(bv0.z, bv0.z), pack2(bv0.w, bv0.w),
                         pack2(bv1.x, bv1.x), pack2(bv1.y, bv1.y),
                         pack2(bv1.z, bv1.z), pack2(bv1.w, bv1.w)};
#pragma unroll
            for (int i = 0; i < 4; i++)
#pragma unroll
                for (int j = 0; j < 8; j++) acc2[i][j] = fma2(a[i], bd[j], acc2[i][j]);
        }
        __syncthreads();
    }

    float acc[8][8];
#pragma unroll
    for (int i = 0; i < 4; i++)
#pragma unroll
        for (int j = 0; j < 8; j++) unpack2(acc2[i][j], acc[2 * i][j], acc[2 * i + 1][j]);

    const int part = bn >> 9;  // uniform per block: 0=Q 1=K 2=V
    if (part == 2) {
#pragma unroll
        for (int i = 0; i < 8; i++) {
            const int m = bm + ty * 8 + i;
            const int bb = m >> 11, s = m & 2047;
#pragma unroll
            for (int jj = 0; jj < 8; jj += 4) {
                const int n = bn + tx * 8 + jj;
                const int hh = (n >> 6) & 7;
                const int d = n & 63;
                float4 v;
                v.x = acc[i][jj + 0] + bias[n + 0];
                v.y = acc[i][jj + 1] + bias[n + 1];
                v.z = acc[i][jj + 2] + bias[n + 2];
                v.w = acc[i][jj + 3] + bias[n + 3];
                *(float4*)&g_v[((size_t)((bb * 8 + hh) * 2048 + s)) * 64 + d] = v;
            }
        }
    } else {
        float* base = part ? g_kt : g_qt;
        const int m0 = bm + ty * 8;
        const int bb = m0 >> 11, s0 = m0 & 2047;
#pragma unroll
        for (int j = 0; j < 8; j++) {
            const int n = bn + tx * 8 + j;
            const int hh = (n >> 6) & 7;
            const int d = n & 63;
            const float bn_ = bias[n];
            float4 lo, hi;
            lo.x = acc[0][j] + bn_; lo.y = acc[1][j] + bn_;
            lo.z = acc[2][j] + bn_; lo.w = acc[3][j] + bn_;
            hi.x = acc[4][j] + bn_; hi.y = acc[5][j] + bn_;
            hi.z = acc[6][j] + bn_; hi.w = acc[7][j] + bn_;
            size_t off = ((size_t)((bb * 8 + hh) * 64 + d)) * 2048 + s0;
            *(float4*)&base[off] = lo;
            *(float4*)&base[off + 4] = hi;
        }
    }
}

// ============================================================
// Kernel 2: gene bias gather.  g_bias[b][q][k] = gene_bias[gi[b][q]][gi[b][k]]
// ============================================================
__global__ __launch_bounds__(256) void bias_gather_kernel(
    const int* __restrict__ gi, const float* __restrict__ gb)
{
    __shared__ int cols[2048];
    const int b = blockIdx.y;
    const int qbase = blockIdx.x * 16;
    for (int i = threadIdx.x; i < 2048; i += 256) cols[i] = gi[b * 2048 + i];
    __syncthreads();
    float* dst = g_bias + ((size_t)b * 2048 + qbase) * 2048;
    for (int q = 0; q < 16; q++) {
        const float* src = gb + (size_t)cols[qbase + q] * 8192;
        float* drow = dst + (size_t)q * 2048;
        for (int k = threadIdx.x * 4; k < 2048; k += 1024) {
            float4 v;
            v.x = src[cols[k + 0]];
            v.y = src[cols[k + 1]];
            v.z = src[cols[k + 2]];
            v.w = src[cols[k + 3]];
            *(float4*)&drow[k] = v;
        }
    }
}

// ============================================================
// Kernel 3: flash attention with f32x2.
// grid (16 q-tiles, 8 heads, 4 batch), 256 threads.
// Q tile 128 rows x 64 keys per step.  Thread (tx 0..15 cols, ty 0..15 rows):
// 8 rows x 4 cols microtile, row-paired f32x2 accumulators.
// Smem: Qt[64][128] (d-major), Kt[64][64] (d-major), V[64][64], Pt[64][128]
// (kk-major, XOR-swizzled).  P rows stay warp-local -> syncwarp only.
// ============================================================
__global__ __launch_bounds__(256, 2) void attn_kernel()
{
    extern __shared__ float smx[];
    float* Qt = smx;            // 8192 floats
    float* Kt = smx + 8192;     // 4096
    float* Vs = smx + 12288;    // 4096
    float* Pt = smx + 16384;    // 8192

    const int qt = blockIdx.x, h = blockIdx.y, b = blockIdx.z;
    const int tid = threadIdx.x;
    const int tx = tid & 15, ty = tid >> 4;

    const size_t bh = (size_t)(b * 8 + h);
    const float* Qg = g_qt + bh * 64 * 2048;
    const float* Kg = g_kt + bh * 64 * 2048;
    const float* Vg = g_v + bh * 2048 * 64;
    const float* Bg = g_bias + ((size_t)b * 2048 + qt * 128) * 2048;

    // load Q tile transposed from gmem (already [d][s])
    for (int i = tid; i < 2048; i += 256) {
        int d = i >> 5, ch = i & 31;
        ((float4*)Qt)[i] = *(const float4*)&Qg[(size_t)d * 2048 + qt * 128 + ch * 4];
    }

    ull o2[4][4];
    float m_i[8], l_i[8];
#pragma unroll
    for (int i = 0; i < 4; i++)
#pragma unroll
        for (int j = 0; j < 4; j++) o2[i][j] = 0ull;
#pragma unroll
    for (int r = 0; r < 8; r++) { m_i[r] = -1e30f; l_i[r] = 0.f; }

    for (int t = 0; t < 32; t++) {
        __syncthreads();   // prev iter's GEMM1/GEMM2 done with Kt/Vs
        for (int i = tid; i < 1024; i += 256) {
            int d = i >> 4, ch = i & 15;
            ((float4*)Kt)[i] = *(const float4*)&Kg[(size_t)d * 2048 + t * 64 + ch * 4];
        }
        {
            const float4* vsrc = (const float4*)(Vg + (size_t)t * 4096);
            for (int i = tid; i < 1024; i += 256) ((float4*)Vs)[i] = vsrc[i];
        }
        __syncthreads();

        // ---- GEMM1: S = Q K^T ----
        ull s2[4][4];
#pragma unroll
        for (int i = 0; i < 4; i++)
#pragma unroll
            for (int j = 0; j < 4; j++) s2[i][j] = 0ull;
#pragma unroll 4
        for (int kk = 0; kk < 64; kk++) {
            const ull* qp = (const ull*)&Qt[kk * 128 + ty * 8];
            ull q[4] = {qp[0], qp[1], qp[2], qp[3]};
            float4 kf = *(const float4*)&Kt[kk * 64 + tx * 4];
            ull kd[4] = {pack2(kf.x, kf.x), pack2(kf.y, kf.y),
                         pack2(kf.z, kf.z), pack2(kf.w, kf.w)};
#pragma unroll
            for (int i = 0; i < 4; i++)
#pragma unroll
                for (int j = 0; j < 4; j++) s2[i][j] = fma2(q[i], kd[j], s2[i][j]);
        }

        // ---- softmax (online) ----
        float sc[8][4];
#pragma unroll
        for (int rp = 0; rp < 4; rp++)
#pragma unroll
            for (int c = 0; c < 4; c++)
                unpack2(s2[rp][c], sc[2 * rp][c], sc[2 * rp + 1][c]);
#pragma unroll
        for (int r = 0; r < 8; r++) {
            float4 bf = *(const float4*)&Bg[(size_t)(ty * 8 + r) * 2048 + t * 64 + tx * 4];
            sc[r][0] = sc[r][0] * 0.125f + bf.x;
            sc[r][1] = sc[r][1] * 0.125f + bf.y;
            sc[r][2] = sc[r][2] * 0.125f + bf.z;
            sc[r][3] = sc[r][3] * 0.125f + bf.w;
        }
        float p[8][4], corr[8];
#pragma unroll
        for (int r = 0; r < 8; r++) {
            float mx = fmaxf(fmaxf(sc[r][0], sc[r][1]), fmaxf(sc[r][2], sc[r][3]));
            mx = fmaxf(mx, __shfl_xor_sync(0xffffffffu, mx, 1));
            mx = fmaxf(mx, __shfl_xor_sync(0xffffffffu, mx, 2));
            mx = fmaxf(mx, __shfl_xor_sync(0xffffffffu, mx, 4));
            mx = fmaxf(mx, __shfl_xor_sync(0xffffffffu, mx, 8));
            float mnew = fmaxf(m_i[r], mx);
            corr[r] = __expf(m_i[r] - mnew);
            m_i[r] = mnew;
            float s = 0.f;
#pragma unroll
            for (int c = 0; c < 4; c++) { p[r][c] = __expf(sc[r][c] - mnew); s += p[r][c]; }
            s += __shfl_xor_sync(0xffffffffu, s, 1);
            s += __shfl_xor_sync(0xffffffffu, s, 2);
            s += __shfl_xor_sync(0xffffffffu, s, 4);
            s += __shfl_xor_sync(0xffffffffu, s, 8);
            l_i[r] = l_i[r] * corr[r] + s;
        }
#pragma unroll
        for (int rp = 0; rp < 4; rp++) {
            ull cp = pack2(corr[2 * rp], corr[2 * rp + 1]);
#pragma unroll
            for (int c = 0; c < 4; c++) o2[rp][c] = mul2(o2[rp][c], cp);
        }

        // ---- write P transposed (swizzled); producer/consumer same warp ----
#pragma unroll
        for (int c = 0; c < 4; c++) {
            int ci = tx * 4 + c;
            int swz = (ci & 7) << 2;
            float4 lo = make_float4(p[0][c], p[1][c], p[2][c], p[3][c]);
            float4 hi = make_float4(p[4][c], p[5][c], p[6][c], p[7][c]);
            *(float4*)&Pt[ci * 128 + ((ty * 8) ^ swz)] = lo;
            *(float4*)&Pt[ci * 128 + ((ty * 8 + 4) ^ swz)] = hi;
        }
        __syncwarp();

        // ---- GEMM2: O += P V ----
#pragma unroll 4
        for (int kk = 0; kk < 64; kk++) {
            int swz = (kk & 7) << 2;
            const float* prow = &Pt[kk * 128];
            ull pp[4];
            pp[0] = *(const ull*)&prow[(ty * 8 + 0) ^ swz];
            pp[1] = *(const ull*)&prow[(ty * 8 + 2) ^ swz];
            pp[2] = *(const ull*)&prow[(ty * 8 + 4) ^ swz];
            pp[3] = *(const ull*)&prow[(ty * 8 + 6) ^ swz];
            float4 vf = *(const float4*)&Vs[kk * 64 + tx * 4];
            ull vd[4] = {pack2(vf.x, vf.x), pack2(vf.y, vf.y),
                         pack2(vf.z, vf.z), pack2(vf.w, vf.w)};
#pragma unroll
            for (int i = 0; i < 4; i++)
#pragma unroll
                for (int j = 0; j < 4; j++) o2[i][j] = fma2(pp[i], vd[j], o2[i][j]);
        }
    }

    // epilogue: write [B][S][H*64+d]
    float o[8][4];
#pragma unroll
    for (int rp = 0; rp < 4; rp++)
#pragma unroll
        for (int c = 0; c < 4; c++)
            unpack2(o2[rp][c], o[2 * rp][c], o[2 * rp + 1][c]);
#pragma unroll
    for (int r = 0; r < 8; r++) {
        float inv = 1.f / l_i[r];
        int s = qt * 128 + ty * 8 + r;
        float4 v = make_float4(o[r][0] * inv, o[r][1] * inv, o[r][2] * inv, o[r][3] * inv);
        *(float4*)&g_ctx[((size_t)(b * 2048 + s)) * 512 + h * 64 + tx * 4] = v;
    }
}

// ============================================================
// Kernel 4: output projection.  out[m][n] = sum_k ctx[m][k]*Wo[n][k] + ob[n]
// M=8192, N=512, K=512.  f32x2 microtile.
// ============================================================
__global__ __launch_bounds__(256) void out_gemm_kernel(
    const float* __restrict__ Wo, const float* __restrict__ ob,
    float* __restrict__ C)
{
    __shared__ __align__(16) float As[16][128];
    __shared__ __align__(16) float Bs[16][128];
    const int bm = blockIdx.y * 128;
    const int bn = blockIdx.x * 128;
    const int tid = threadIdx.x;
    const int tx = tid & 15, ty = tid >> 4;
    const int lr = tid >> 2;
    const int lc = (tid & 3) << 2;
    const float* A = g_ctx;

    ull acc2[4][8];
#pragma unroll
    for (int i = 0; i < 4; i++)
#pragma unroll
        for (int j = 0; j < 8; j++) acc2[i][j] = 0ull;

    for (int kt = 0; kt < 512; kt += 16) {
        float4 a0 = *(const float4*)&A[(size_t)(bm + lr) * 512 + kt + lc];
        float4 a1 = *(const float4*)&A[(size_t)(bm + lr + 64) * 512 + kt + lc];
        float4 b0 = *(const float4*)&Wo[(size_t)(bn + lr) * 512 + kt + lc];
        float4 b1 = *(const float4*)&Wo[(size_t)(bn + lr + 64) * 512 + kt + lc];
        As[lc + 0][lr] = a0.x; As[lc + 1][lr] = a0.y; As[lc + 2][lr] = a0.z; As[lc + 3][lr] = a0.w;
        As[lc + 0][lr + 64] = a1.x; As[lc + 1][lr + 64] = a1.y; As[lc + 2][lr + 64] = a1.z; As[lc + 3][lr + 64] = a1.w;
        Bs[lc + 0][lr] = b0.x; Bs[lc + 1][lr] = b0.y; Bs[lc + 2][lr] = b0.z; Bs[lc + 3][lr] = b0.w;
        Bs[lc + 0][lr + 64] = b1.x; Bs[lc + 1][lr + 64] = b1.y; Bs[lc + 2][lr + 64] = b1.z; Bs[lc + 3][lr + 64] = b1.w;
        __syncthreads();
#pragma unroll
        for (int kk = 0; kk < 16; kk++) {
            const ull* ap = (const ull*)&As[kk][ty * 8];
            ull a[4] = {ap[0], ap[1], ap[2], ap[3]};
            float4 bv0 = ((const float4*)Bs[kk])[tx * 2];
            float4 bv1 = ((const float4*)Bs[kk])[tx * 2 + 1];
            ull bd[8] = {pack2(bv0.x, bv0.x), pack2(bv0.y, bv0.y),
                         pack2(bv0.z, bv0.z), pack2(bv0.w, bv0.w),
                         pack2(bv1.x, bv1.x), pack2(bv1.y, bv1.y),
                         pack2(bv1.z, bv1.z), pack2(bv1.w, bv1.w)};
#pragma unroll
            for (int i = 0; i < 4; i++)
#pragma unroll
                for (int j = 0; j < 8; j++) acc2[i][j] = fma2(a[i], bd[j], acc2[i][j]);
        }
        __syncthreads();
    }

    float acc[8][8];
#pragma unroll
    for (int i = 0; i < 4; i++)
#pragma unroll
        for (int j = 0; j < 8; j++) unpack2(acc2[i][j], acc[2 * i][j], acc[2 * i + 1][j]);

#pragma unroll
    for (int i = 0; i < 8; i++) {
        const int m = bm + ty * 8 + i;
#pragma unroll
        for (int jj = 0; jj < 8; jj += 4) {
            const int n = bn + tx * 8 + jj;
            float4 v;
            v.x = acc[i][jj + 0] + ob[n + 0];
            v.y = acc[i][jj + 1] + ob[n + 1];
            v.z = acc[i][jj + 2] + ob[n + 2];
            v.w = acc[i][jj + 3] + ob[n + 3];
            *(float4*)&C[(size_t)m * 512 + n] = v;
        }
    }
}

// ============================================================
extern "C" void kernel_launch(void* const* d_in, const int* in_sizes, int n_in,
                              void* d_out, int out_size)
{
    const float* query = (const float*)d_in[0];
    const int*   gidx  = (const int*)d_in[1];
    const float* ipw   = (const float*)d_in[2];
    const float* ipb   = (const float*)d_in[3];
    const float* outw  = (const float*)d_in[4];
    const float* outb  = (const float*)d_in[5];
    const float* gbias = (const float*)d_in[6];
    float* out = (float*)d_out;

    cudaFuncSetAttribute(attn_kernel, cudaFuncAttributeMaxDynamicSharedMemorySize, 98304);

    qkv_gemm_kernel<<<dim3(12, 64), 256>>>(query, ipw, ipb);
    bias_gather_kernel<<<dim3(128, 4), 256>>>(gidx, gbias);
    attn_kernel<<<dim3(16, 8, 4), 256, 98304>>>();
    out_gemm_kernel<<<dim3(4, 64), 256>>>(outw, outb, out);
}

// round 3
// speedup vs baseline: 2.7597x; 2.7597x over previous
#include <cuda_runtime.h>

#define B_ 4
#define S_ 2048
#define H_ 8
#define DM_ 512

// ---------------- device scratch (no cudaMalloc allowed) ----------------
__device__ float g_q[B_ * H_ * S_ * 64];       // [B*H][S][D]
__device__ float g_k[B_ * H_ * S_ * 64];
__device__ float g_v[B_ * H_ * S_ * 64];
__device__ float g_bias[(size_t)B_ * S_ * S_]; // [B][S][S] gathered gene bias
__device__ float g_ctx[B_ * S_ * DM_];         // [B][S][DM]

// ---------------- tf32 mma helpers ----------------
__device__ __forceinline__ unsigned tf32_of(float x) {
    unsigned r; asm("cvt.rna.tf32.f32 %0, %1;" : "=r"(r) : "f"(x)); return r;
}
__device__ __forceinline__ float tf32f(float x) {
    return __uint_as_float(tf32_of(x));
}
__device__ __forceinline__ void mma8(float* d, const unsigned* a, unsigned b0, unsigned b1) {
    asm volatile(
        "mma.sync.aligned.m16n8k8.row.col.f32.tf32.tf32.f32 "
        "{%0,%1,%2,%3},{%4,%5,%6,%7},{%8,%9},{%0,%1,%2,%3};"
        : "+f"(d[0]), "+f"(d[1]), "+f"(d[2]), "+f"(d[3])
        : "r"(a[0]), "r"(a[1]), "r"(a[2]), "r"(a[3]), "r"(b0), "r"(b1));
}
__device__ __forceinline__ unsigned uof(float x) { return __float_as_uint(x); }

// ============================================================
// Kernel 1: QKV projection (tensor core, tf32).
// qkv[m][n] = sum_k A[m][k]*W[n][k] + bias[n]
// M=8192, N=1536, K=512.  Block tile 128x128, BK=32, 8 warps (2x4),
// warp tile 64x32 = 4 mblocks x 4 nblocks of m16n8k8.
// ============================================================
__global__ __launch_bounds__(256) void qkv_gemm_kernel(
    const float* __restrict__ A, const float* __restrict__ W,
    const float* __restrict__ bias)
{
    __shared__ __align__(16) float As[128 * 36];
    __shared__ __align__(16) float Bs[128 * 36];
    const int bm = blockIdx.y * 128;
    const int bn = blockIdx.x * 128;
    const int tid = threadIdx.x;
    const int w = tid >> 5, lane = tid & 31;
    const int g = lane >> 2, c = lane & 3;
    const int wm = (w >> 2) * 64, wn = (w & 3) * 32;

    float acc[4][4][4];
#pragma unroll
    for (int nb = 0; nb < 4; nb++) {
        const int n = bn + wn + nb * 8 + 2 * c;
        const float b0 = bias[n], b1 = bias[n + 1];
#pragma unroll
        for (int mb = 0; mb < 4; mb++) {
            acc[mb][nb][0] = b0; acc[mb][nb][1] = b1;
            acc[mb][nb][2] = b0; acc[mb][nb][3] = b1;
        }
    }

    for (int kt = 0; kt < 512; kt += 32) {
        __syncthreads();
#pragma unroll
        for (int j = 0; j < 4; j++) {
            const int idx = tid + 256 * j;
            const int row = idx >> 3, c4 = (idx & 7) * 4;
            float4 av = *(const float4*)&A[(size_t)(bm + row) * 512 + kt + c4];
            float4 bv = *(const float4*)&W[(size_t)(bn + row) * 512 + kt + c4];
            av.x = tf32f(av.x); av.y = tf32f(av.y); av.z = tf32f(av.z); av.w = tf32f(av.w);
            bv.x = tf32f(bv.x); bv.y = tf32f(bv.y); bv.z = tf32f(bv.z); bv.w = tf32f(bv.w);
            *(float4*)&As[row * 36 + c4] = av;
            *(float4*)&Bs[row * 36 + c4] = bv;
        }
        __syncthreads();
#pragma unroll
        for (int ks = 0; ks < 4; ks++) {
            unsigned a[4][4];
#pragma unroll
            for (int mb = 0; mb < 4; mb++) {
                const int r = wm + mb * 16 + g;
                a[mb][0] = uof(As[r * 36 + ks * 8 + c]);
                a[mb][1] = uof(As[(r + 8) * 36 + ks * 8 + c]);
                a[mb][2] = uof(As[r * 36 + ks * 8 + c + 4]);
                a[mb][3] = uof(As[(r + 8) * 36 + ks * 8 + c + 4]);
            }
#pragma unroll
            for (int nb = 0; nb < 4; nb++) {
                const int nr = wn + nb * 8 + g;
                const unsigned b0 = uof(Bs[nr * 36 + ks * 8 + c]);
                const unsigned b1 = uof(Bs[nr * 36 + ks * 8 + c + 4]);
#pragma unroll
                for (int mb = 0; mb < 4; mb++) mma8(acc[mb][nb], a[mb], b0, b1);
            }
        }
    }

    const int part = bn >> 9;  // uniform per block: 0=Q 1=K 2=V
    float* dst = (part == 0) ? g_q : ((part == 1) ? g_k : g_v);
#pragma unroll
    for (int mb = 0; mb < 4; mb++) {
        const int m0 = bm + wm + mb * 16 + g;
#pragma unroll
        for (int nb = 0; nb < 4; nb++) {
            const int n = bn + wn + nb * 8 + 2 * c;
            const int h = (n >> 6) & 7;
            const int d = n & 63;
            const int bb0 = m0 >> 11, s0 = m0 & 2047;
            const int bb1 = (m0 + 8) >> 11, s1 = (m0 + 8) & 2047;
            *(float2*)&dst[((size_t)((bb0 * 8 + h) * 2048 + s0)) * 64 + d] =
                make_float2(acc[mb][nb][0], acc[mb][nb][1]);
            *(float2*)&dst[((size_t)((bb1 * 8 + h) * 2048 + s1)) * 64 + d] =
                make_float2(acc[mb][nb][2], acc[mb][nb][3]);
        }
    }
}

// ============================================================
// Kernel 2: gene bias gather.  g_bias[b][q][k] = gene_bias[gi[b][q]][gi[b][k]]
// ============================================================
__global__ __launch_bounds__(256) void bias_gather_kernel(
    const int* __restrict__ gi, const float* __restrict__ gb)
{
    __shared__ int cols[2048];
    const int b = blockIdx.y;
    const int qbase = blockIdx.x * 16;
    for (int i = threadIdx.x; i < 2048; i += 256) cols[i] = gi[b * 2048 + i];
    __syncthreads();
    float* dst = g_bias + ((size_t)b * 2048 + qbase) * 2048;
    for (int q = 0; q < 16; q++) {
        const float* src = gb + (size_t)cols[qbase + q] * 8192;
        float* drow = dst + (size_t)q * 2048;
        for (int k = threadIdx.x * 4; k < 2048; k += 1024) {
            float4 v;
            v.x = src[cols[k + 0]];
            v.y = src[cols[k + 1]];
            v.z = src[cols[k + 2]];
            v.w = src[cols[k + 3]];
            *(float4*)&drow[k] = v;
        }
    }
}

// ============================================================
// Kernel 3: flash attention (tensor core, tf32).
// grid (16 q-tiles, 8 heads, 4 batch), 256 threads (8 warps).
// Warp w owns q rows [16w,16w+16).  Q frags in registers (pre-scaled 1/8).
// Per 64-key tile: scores init = gene bias (mma accumulator), GEMM1,
// online softmax in D-frag layout, shfl-transpose P -> A-frags, GEMM2.
// Smem: Ks[64][68], Vs[64][72] (pad for conflict-free fragment LDS).
// ============================================================
__global__ __launch_bounds__(256) void attn_kernel()
{
    __shared__ __align__(16) float Ks[64 * 68];
    __shared__ __align__(16) float Vs[64 * 72];

    const int qt = blockIdx.x, h = blockIdx.y, b = blockIdx.z;
    const int tid = threadIdx.x;
    const int w = tid >> 5, lane = tid & 31;
    const int g = lane >> 2, c = lane & 3;
    const int base = lane & ~3;

    const size_t bh = (size_t)(b * 8 + h);
    const float* Qg = g_q + bh * 2048 * 64;
    const float* Kg = g_k + bh * 2048 * 64;
    const float* Vg = g_v + bh * 2048 * 64;
    const float* Bg = g_bias + ((size_t)b * 2048 + qt * 128) * 2048;

    // Q fragments, held for the whole kernel (scaled by 1/8)
    unsigned qA[8][4];
    {
        const int r0 = qt * 128 + 16 * w + g;
#pragma unroll
        for (int kb = 0; kb < 8; kb++) {
            qA[kb][0] = tf32_of(Qg[(size_t)r0 * 64 + kb * 8 + c] * 0.125f);
            qA[kb][1] = tf32_of(Qg[(size_t)(r0 + 8) * 64 + kb * 8 + c] * 0.125f);
            qA[kb][2] = tf32_of(Qg[(size_t)r0 * 64 + kb * 8 + c + 4] * 0.125f);
            qA[kb][3] = tf32_of(Qg[(size_t)(r0 + 8) * 64 + kb * 8 + c + 4] * 0.125f);
        }
    }

    float o[8][4];
#pragma unroll
    for (int nb = 0; nb < 8; nb++)
#pragma unroll
        for (int i = 0; i < 4; i++) o[nb][i] = 0.f;
    float m0 = -1e30f, m1 = -1e30f, l0 = 0.f, l1 = 0.f;

    for (int t = 0; t < 32; t++) {
        __syncthreads();   // previous tile's GEMMs done with Ks/Vs
#pragma unroll
        for (int j = 0; j < 4; j++) {
            const int idx = tid + 256 * j;
            const int row = idx >> 4, c4 = (idx & 15) * 4;
            float4 kv = *(const float4*)&Kg[(size_t)(t * 64 + row) * 64 + c4];
            float4 vv = *(const float4*)&Vg[(size_t)(t * 64 + row) * 64 + c4];
            kv.x = tf32f(kv.x); kv.y = tf32f(kv.y); kv.z = tf32f(kv.z); kv.w = tf32f(kv.w);
            vv.x = tf32f(vv.x); vv.y = tf32f(vv.y); vv.z = tf32f(vv.z); vv.w = tf32f(vv.w);
            *(float4*)&Ks[row * 68 + c4] = kv;
            *(float4*)&Vs[row * 72 + c4] = vv;
        }

        // scores accumulator initialized with gene bias (LDG under staging+GEMM1)
        float s[8][4];
        {
            const float* brow0 = Bg + (size_t)(16 * w + g) * 2048 + t * 64;
            const float* brow1 = brow0 + 8 * 2048;
#pragma unroll
            for (int nb = 0; nb < 8; nb++) {
                float2 blo = *(const float2*)&brow0[nb * 8 + 2 * c];
                float2 bhi = *(const float2*)&brow1[nb * 8 + 2 * c];
                s[nb][0] = blo.x; s[nb][1] = blo.y;
                s[nb][2] = bhi.x; s[nb][3] = bhi.y;
            }
        }
        __syncthreads();

        // ---- GEMM1: S = bias + (Q/8) K^T ----
#pragma unroll
        for (int kb = 0; kb < 8; kb++) {
#pragma unroll
            for (int nb = 0; nb < 8; nb++) {
                const int kr = nb * 8 + g;
                const unsigned b0 = uof(Ks[kr * 68 + kb * 8 + c]);
                const unsigned b1 = uof(Ks[kr * 68 + kb * 8 + c + 4]);
                mma8(s[nb], qA[kb], b0, b1);
            }
        }

        // ---- online softmax (rows g and g+8 of this warp's strip) ----
        float mx0 = -1e30f, mx1 = -1e30f;
#pragma unroll
        for (int nb = 0; nb < 8; nb++) {
            mx0 = fmaxf(mx0, fmaxf(s[nb][0], s[nb][1]));
            mx1 = fmaxf(mx1, fmaxf(s[nb][2], s[nb][3]));
        }
        mx0 = fmaxf(mx0, __shfl_xor_sync(0xffffffffu, mx0, 1));
        mx0 = fmaxf(mx0, __shfl_xor_sync(0xffffffffu, mx0, 2));
        mx1 = fmaxf(mx1, __shfl_xor_sync(0xffffffffu, mx1, 1));
        mx1 = fmaxf(mx1, __shfl_xor_sync(0xffffffffu, mx1, 2));
        const float mn0 = fmaxf(m0, mx0), mn1 = fmaxf(m1, mx1);
        const float corr0 = __expf(m0 - mn0), corr1 = __expf(m1 - mn1);
        m0 = mn0; m1 = mn1;
        float sum0 = 0.f, sum1 = 0.f;
#pragma unroll
        for (int nb = 0; nb < 8; nb++) {
            s[nb][0] = __expf(s[nb][0] - mn0);
            s[nb][1] = __expf(s[nb][1] - mn0);
            s[nb][2] = __expf(s[nb][2] - mn1);
            s[nb][3] = __expf(s[nb][3] - mn1);
            sum0 += s[nb][0] + s[nb][1];
            sum1 += s[nb][2] + s[nb][3];
        }
        sum0 += __shfl_xor_sync(0xffffffffu, sum0, 1);
        sum0 += __shfl_xor_sync(0xffffffffu, sum0, 2);
        sum1 += __shfl_xor_sync(0xffffffffu, sum1, 1);
        sum1 += __shfl_xor_sync(0xffffffffu, sum1, 2);
        l0 = l0 * corr0 + sum0;
        l1 = l1 * corr1 + sum1;
#pragma unroll
        for (int nb = 0; nb < 8; nb++) {
            o[nb][0] *= corr0; o[nb][1] *= corr0;
            o[nb][2] *= corr1; o[nb][3] *= corr1;
        }

        // ---- GEMM2: O += P V.  P: D-frag -> A-frag via quad shuffles ----
#pragma unroll
        for (int kb = 0; kb < 8; kb++) {
            const int s0l = base | (c >> 1);
            const int s1l = s0l + 2;
            const float p0 = s[kb][0], p1 = s[kb][1], p2 = s[kb][2], p3 = s[kb][3];
            const float x0 = __shfl_sync(0xffffffffu, p0, s0l);
            const float x1 = __shfl_sync(0xffffffffu, p1, s0l);
            const float x2 = __shfl_sync(0xffffffffu, p0, s1l);
            const float x3 = __shfl_sync(0xffffffffu, p1, s1l);
            const float y0 = __shfl_sync(0xffffffffu, p2, s0l);
            const float y1 = __shfl_sync(0xffffffffu, p3, s0l);
            const float y2 = __shfl_sync(0xffffffffu, p2, s1l);
            const float y3 = __shfl_sync(0xffffffffu, p3, s1l);
            unsigned pa[4];
            pa[0] = tf32_of((c & 1) ? x1 : x0);
            pa[2] = tf32_of((c & 1) ? x3 : x2);
            pa[1] = tf32_of((c & 1) ? y1 : y0);
            pa[3] = tf32_of((c & 1) ? y3 : y2);
#pragma unroll
            for (int nb = 0; nb < 8; nb++) {
                const unsigned b0 = uof(Vs[(kb * 8 + c) * 72 + nb * 8 + g]);
                const unsigned b1 = uof(Vs[(kb * 8 + c + 4) * 72 + nb * 8 + g]);
                mma8(o[nb], pa, b0, b1);
            }
        }
    }

    // epilogue: write [B][S][H*64+d]
    const float inv0 = 1.f / l0, inv1 = 1.f / l1;
    const int row0 = b * 2048 + qt * 128 + 16 * w + g;
#pragma unroll
    for (int nb = 0; nb < 8; nb++) {
        const int d = h * 64 + nb * 8 + 2 * c;
        *(float2*)&g_ctx[(size_t)row0 * 512 + d] =
            make_float2(o[nb][0] * inv0, o[nb][1] * inv0);
        *(float2*)&g_ctx[(size_t)(row0 + 8) * 512 + d] =
            make_float2(o[nb][2] * inv1, o[nb][3] * inv1);
    }
}

// ============================================================
// Kernel 4: output projection (tensor core, tf32).
// out[m][n] = sum_k ctx[m][k]*Wo[n][k] + ob[n].  M=8192, N=512, K=512.
// ============================================================
__global__ __launch_bounds__(256) void out_gemm_kernel(
    const float* __restrict__ Wo, const float* __restrict__ ob,
    float* __restrict__ C)
{
    __shared__ __align__(16) float As[128 * 36];
    __shared__ __align__(16) float Bs[128 * 36];
    const int bm = blockIdx.y * 128;
    const int bn = blockIdx.x * 128;
    const int tid = threadIdx.x;
    const int w = tid >> 5, lane = tid & 31;
    const int g = lane >> 2, c = lane & 3;
    const int wm = (w >> 2) * 64, wn = (w & 3) * 32;
    const float* A = g_ctx;

    float acc[4][4][4];
#pragma unroll
    for (int nb = 0; nb < 4; nb++) {
        const int n = bn + wn + nb * 8 + 2 * c;
        const float b0 = ob[n], b1 = ob[n + 1];
#pragma unroll
        for (int mb = 0; mb < 4; mb++) {
            acc[mb][nb][0] = b0; acc[mb][nb][1] = b1;
            acc[mb][nb][2] = b0; acc[mb][nb][3] = b1;
        }
    }

    for (int kt = 0; kt < 512; kt += 32) {
        __syncthreads();
#pragma unroll
        for (int j = 0; j < 4; j++) {
            const int idx = tid + 256 * j;
            const int row = idx >> 3, c4 = (idx & 7) * 4;
            float4 av = *(const float4*)&A[(size_t)(bm + row) * 512 + kt + c4];
            float4 bv = *(const float4*)&Wo[(size_t)(bn + row) * 512 + kt + c4];
            av.x = tf32f(av.x); av.y = tf32f(av.y); av.z = tf32f(av.z); av.w = tf32f(av.w);
            bv.x = tf32f(bv.x); bv.y = tf32f(bv.y); bv.z = tf32f(bv.z); bv.w = tf32f(bv.w);
            *(float4*)&As[row * 36 + c4] = av;
            *(float4*)&Bs[row * 36 + c4] = bv;
        }
        __syncthreads();
#pragma unroll
        for (int ks = 0; ks < 4; ks++) {
            unsigned a[4][4];
#pragma unroll
            for (int mb = 0; mb < 4; mb++) {
                const int r = wm + mb * 16 + g;
                a[mb][0] = uof(As[r * 36 + ks * 8 + c]);
                a[mb][1] = uof(As[(r + 8) * 36 + ks * 8 + c]);
                a[mb][2] = uof(As[r * 36 + ks * 8 + c + 4]);
                a[mb][3] = uof(As[(r + 8) * 36 + ks * 8 + c + 4]);
            }
#pragma unroll
            for (int nb = 0; nb < 4; nb++) {
                const int nr = wn + nb * 8 + g;
                const unsigned b0 = uof(Bs[nr * 36 + ks * 8 + c]);
                const unsigned b1 = uof(Bs[nr * 36 + ks * 8 + c + 4]);
#pragma unroll
                for (int mb = 0; mb < 4; mb++) mma8(acc[mb][nb], a[mb], b0, b1);
            }
        }
    }

#pragma unroll
    for (int mb = 0; mb < 4; mb++) {
        const int m0 = bm + wm + mb * 16 + g;
#pragma unroll
        for (int nb = 0; nb < 4; nb++) {
            const int n = bn + wn + nb * 8 + 2 * c;
            *(float2*)&C[(size_t)m0 * 512 + n] =
                make_float2(acc[mb][nb][0], acc[mb][nb][1]);
            *(float2*)&C[(size_t)(m0 + 8) * 512 + n] =
                make_float2(acc[mb][nb][2], acc[mb][nb][3]);
        }
    }
}

// ============================================================
extern "C" void kernel_launch(void* const* d_in, const int* in_sizes, int n_in,
                              void* d_out, int out_size)
{
    const float* query = (const float*)d_in[0];
    const int*   gidx  = (const int*)d_in[1];
    const float* ipw   = (const float*)d_in[2];
    const float* ipb   = (const float*)d_in[3];
    const float* outw  = (const float*)d_in[4];
    const float* outb  = (const float*)d_in[5];
    const float* gbias = (const float*)d_in[6];
    float* out = (float*)d_out;

    qkv_gemm_kernel<<<dim3(12, 64), 256>>>(query, ipw, ipb);
    bias_gather_kernel<<<dim3(128, 4), 256>>>(gidx, gbias);
    attn_kernel<<<dim3(16, 8, 4), 256>>>();
    out_gemm_kernel<<<dim3(4, 64), 256>>>(outw, outb, out);
}

// round 4
// speedup vs baseline: 2.9112x; 1.0549x over previous
#include <cuda_runtime.h>
#include <cuda_fp16.h>

#define B_ 4
#define S_ 2048
#define H_ 8
#define DM_ 512

// ---------------- device scratch (no cudaMalloc allowed) ----------------
__device__ float g_qr[B_ * S_ * DM_];           // tf32-rounded query
__device__ float g_wr[3 * DM_ * DM_];           // tf32-rounded in_proj_weight
__device__ float g_wor[DM_ * DM_];              // tf32-rounded out_w
__device__ float g_q[B_ * H_ * S_ * 64];        // [B*H][S][D] (tf32-rounded)
__device__ float g_k[B_ * H_ * S_ * 64];
__device__ float g_v[B_ * H_ * S_ * 64];
__device__ __half g_bias[(size_t)B_ * S_ * S_]; // [B][S][S] gathered bias, fp16
__device__ float g_ctx[B_ * S_ * DM_];          // [B][S][DM] (tf32-rounded)

// ---------------- helpers ----------------
__device__ __forceinline__ unsigned tf32_of(float x) {
    unsigned r; asm("cvt.rna.tf32.f32 %0, %1;" : "=r"(r) : "f"(x)); return r;
}
__device__ __forceinline__ float tf32f(float x) {
    return __uint_as_float(tf32_of(x));
}
__device__ __forceinline__ void mma8(float* d, const unsigned* a, unsigned b0, unsigned b1) {
    asm volatile(
        "mma.sync.aligned.m16n8k8.row.col.f32.tf32.tf32.f32 "
        "{%0,%1,%2,%3},{%4,%5,%6,%7},{%8,%9},{%0,%1,%2,%3};"
        : "+f"(d[0]), "+f"(d[1]), "+f"(d[2]), "+f"(d[3])
        : "r"(a[0]), "r"(a[1]), "r"(a[2]), "r"(a[3]), "r"(b0), "r"(b1));
}
__device__ __forceinline__ unsigned uof(float x) { return __float_as_uint(x); }
__device__ __forceinline__ unsigned sptr(const void* p) {
    return (unsigned)__cvta_generic_to_shared(p);
}
__device__ __forceinline__ void cpa16(unsigned s, const void* g) {
    asm volatile("cp.async.cg.shared.global [%0], [%1], 16;" :: "r"(s), "l"(g));
}
#define CP_COMMIT() asm volatile("cp.async.commit_group;")
#define CP_WAIT0()  asm volatile("cp.async.wait_group 0;")

// ============================================================
// Kernel 0: pre-round fp32 -> tf32 bits (grid-stride, float4)
// ============================================================
__global__ __launch_bounds__(256) void preround_kernel(
    const float4* __restrict__ src, float4* __restrict__ dst, int n4)
{
    for (int i = blockIdx.x * 256 + threadIdx.x; i < n4; i += gridDim.x * 256) {
        float4 v = src[i];
        v.x = tf32f(v.x); v.y = tf32f(v.y); v.z = tf32f(v.z); v.w = tf32f(v.w);
        dst[i] = v;
    }
}

// ============================================================
// Kernel 1: QKV projection.  tf32 mma, cp.async 2-stage, BK=16.
// Block 128x128, 8 warps (2x4), warp 64x32.  Epilogue re-rounds to tf32.
// ============================================================
__global__ __launch_bounds__(256) void qkv_gemm_kernel(const float* __restrict__ bias)
{
    __shared__ __align__(16) float As[2][128 * 20];
    __shared__ __align__(16) float Bs[2][128 * 20];
    const float* __restrict__ A = g_qr;
    const float* __restrict__ W = g_wr;
    const int bm = blockIdx.y * 128;
    const int bn = blockIdx.x * 128;
    const int tid = threadIdx.x;
    const int w = tid >> 5, lane = tid & 31;
    const int g = lane >> 2, c = lane & 3;
    const int wm = (w >> 2) * 64, wn = (w & 3) * 32;

    const int srow0 = tid >> 2, sc4_0 = (tid & 3) * 4;
    const int srow1 = (tid + 256) >> 2, sc4_1 = sc4_0;  // (idx&3) unchanged

    float acc[4][4][4];
#pragma unroll
    for (int nb = 0; nb < 4; nb++) {
        const int n = bn + wn + nb * 8 + 2 * c;
        const float b0 = bias[n], b1 = bias[n + 1];
#pragma unroll
        for (int mb = 0; mb < 4; mb++) {
            acc[mb][nb][0] = b0; acc[mb][nb][1] = b1;
            acc[mb][nb][2] = b0; acc[mb][nb][3] = b1;
        }
    }

    // stage tile 0
    {
        unsigned sa = sptr(&As[0][0]), sb = sptr(&Bs[0][0]);
        cpa16(sa + (srow0 * 20 + sc4_0) * 4, &A[(size_t)(bm + srow0) * 512 + sc4_0]);
        cpa16(sa + (srow1 * 20 + sc4_1) * 4, &A[(size_t)(bm + srow1) * 512 + sc4_1]);
        cpa16(sb + (srow0 * 20 + sc4_0) * 4, &W[(size_t)(bn + srow0) * 512 + sc4_0]);
        cpa16(sb + (srow1 * 20 + sc4_1) * 4, &W[(size_t)(bn + srow1) * 512 + sc4_1]);
        CP_COMMIT();
    }

    for (int t = 0; t < 32; t++) {
        CP_WAIT0();
        __syncthreads();
        const int buf = t & 1;
        if (t + 1 < 32) {
            const int kt = (t + 1) * 16;
            unsigned sa = sptr(&As[buf ^ 1][0]), sb = sptr(&Bs[buf ^ 1][0]);
            cpa16(sa + (srow0 * 20 + sc4_0) * 4, &A[(size_t)(bm + srow0) * 512 + kt + sc4_0]);
            cpa16(sa + (srow1 * 20 + sc4_1) * 4, &A[(size_t)(bm + srow1) * 512 + kt + sc4_1]);
            cpa16(sb + (srow0 * 20 + sc4_0) * 4, &W[(size_t)(bn + srow0) * 512 + kt + sc4_0]);
            cpa16(sb + (srow1 * 20 + sc4_1) * 4, &W[(size_t)(bn + srow1) * 512 + kt + sc4_1]);
            CP_COMMIT();
        }
        const float* as = As[buf];
        const float* bs = Bs[buf];
#pragma unroll
        for (int ks = 0; ks < 2; ks++) {
            unsigned a[4][4];
#pragma unroll
            for (int mb = 0; mb < 4; mb++) {
                const int r = wm + mb * 16 + g;
                a[mb][0] = uof(as[r * 20 + ks * 8 + c]);
                a[mb][1] = uof(as[(r + 8) * 20 + ks * 8 + c]);
                a[mb][2] = uof(as[r * 20 + ks * 8 + c + 4]);
                a[mb][3] = uof(as[(r + 8) * 20 + ks * 8 + c + 4]);
            }
#pragma unroll
            for (int nb = 0; nb < 4; nb++) {
                const int nr = wn + nb * 8 + g;
                const unsigned b0 = uof(bs[nr * 20 + ks * 8 + c]);
                const unsigned b1 = uof(bs[nr * 20 + ks * 8 + c + 4]);
#pragma unroll
                for (int mb = 0; mb < 4; mb++) mma8(acc[mb][nb], a[mb], b0, b1);
            }
        }
    }

    const int part = bn >> 9;  // 0=Q 1=K 2=V (uniform per block)
    float* dst = (part == 0) ? g_q : ((part == 1) ? g_k : g_v);
#pragma unroll
    for (int mb = 0; mb < 4; mb++) {
        const int m0 = bm + wm + mb * 16 + g;
#pragma unroll
        for (int nb = 0; nb < 4; nb++) {
            const int n = bn + wn + nb * 8 + 2 * c;
            const int h = (n >> 6) & 7;
            const int d = n & 63;
            const int bb0 = m0 >> 11, s0 = m0 & 2047;
            const int bb1 = (m0 + 8) >> 11, s1 = (m0 + 8) & 2047;
            *(float2*)&dst[((size_t)((bb0 * 8 + h) * 2048 + s0)) * 64 + d] =
                make_float2(tf32f(acc[mb][nb][0]), tf32f(acc[mb][nb][1]));
            *(float2*)&dst[((size_t)((bb1 * 8 + h) * 2048 + s1)) * 64 + d] =
                make_float2(tf32f(acc[mb][nb][2]), tf32f(acc[mb][nb][3]));
        }
    }
}

// ============================================================
// Kernel 2: gene bias gather -> fp16 table.
// ============================================================
__global__ __launch_bounds__(256) void bias_gather_kernel(
    const int* __restrict__ gi, const float* __restrict__ gb)
{
    __shared__ int cols[2048];
    const int b = blockIdx.y;
    const int qbase = blockIdx.x * 16;
    for (int i = threadIdx.x; i < 2048; i += 256) cols[i] = gi[b * 2048 + i];
    __syncthreads();
    __half* dst = g_bias + ((size_t)b * 2048 + qbase) * 2048;
    for (int q = 0; q < 16; q++) {
        const float* src = gb + (size_t)cols[qbase + q] * 8192;
        __half* drow = dst + (size_t)q * 2048;
        for (int k = threadIdx.x * 4; k < 2048; k += 1024) {
            float4 v;
            v.x = src[cols[k + 0]];
            v.y = src[cols[k + 1]];
            v.z = src[cols[k + 2]];
            v.w = src[cols[k + 3]];
            __half2 hlo = __floats2half2_rn(v.x, v.y);
            __half2 hhi = __floats2half2_rn(v.z, v.w);
            uint2 u = make_uint2(*(unsigned*)&hlo, *(unsigned*)&hhi);
            *(uint2*)&drow[k] = u;
        }
    }
}

// ============================================================
// Kernel 3: flash attention (tf32 mma, cp.async 2-stage K/V).
// grid (16 qtiles, 8 heads, 4 batch), 256 threads (8 warps).
// Inputs already tf32-rounded; bias fp16 as accumulator init.
// ============================================================
__global__ __launch_bounds__(256) void attn_kernel()
{
    extern __shared__ __align__(16) float sm[];
    float* KsB = sm;                 // [2][64*68]
    float* VsB = sm + 2 * 64 * 68;   // [2][64*72]

    const int qt = blockIdx.x, h = blockIdx.y, b = blockIdx.z;
    const int tid = threadIdx.x;
    const int w = tid >> 5, lane = tid & 31;
    const int g = lane >> 2, c = lane & 3;
    const int base = lane & ~3;

    const size_t bh = (size_t)(b * 8 + h);
    const float* Qg = g_q + bh * 2048 * 64;
    const float* Kg = g_k + bh * 2048 * 64;
    const float* Vg = g_v + bh * 2048 * 64;
    const __half* Bg = g_bias + ((size_t)b * 2048 + qt * 128) * 2048;

    const int srow = tid >> 4, sc4 = (tid & 15) * 4;  // staging coords (j stride adds 16 rows)

    // Q fragments, pre-rounded; *0.125f is exponent-only (tf32-exact)
    unsigned qA[8][4];
    {
        const int r0 = qt * 128 + 16 * w + g;
#pragma unroll
        for (int kb = 0; kb < 8; kb++) {
            qA[kb][0] = uof(0.125f * Qg[(size_t)r0 * 64 + kb * 8 + c]);
            qA[kb][1] = uof(0.125f * Qg[(size_t)(r0 + 8) * 64 + kb * 8 + c]);
            qA[kb][2] = uof(0.125f * Qg[(size_t)r0 * 64 + kb * 8 + c + 4]);
            qA[kb][3] = uof(0.125f * Qg[(size_t)(r0 + 8) * 64 + kb * 8 + c + 4]);
        }
    }

    float o[8][4];
#pragma unroll
    for (int nb = 0; nb < 8; nb++)
#pragma unroll
        for (int i = 0; i < 4; i++) o[nb][i] = 0.f;
    float m0 = -1e30f, m1 = -1e30f, l0 = 0.f, l1 = 0.f;

    // stage tile 0
    {
        unsigned sk = sptr(KsB), sv = sptr(VsB);
#pragma unroll
        for (int j = 0; j < 4; j++) {
            const int row = srow + j * 16;
            cpa16(sk + (row * 68 + sc4) * 4, &Kg[(size_t)row * 64 + sc4]);
            cpa16(sv + (row * 72 + sc4) * 4, &Vg[(size_t)row * 64 + sc4]);
        }
        CP_COMMIT();
    }

    for (int t = 0; t < 32; t++) {
        CP_WAIT0();
        __syncthreads();
        const int buf = t & 1;
        if (t + 1 < 32) {
            unsigned sk = sptr(KsB + (buf ^ 1) * 64 * 68);
            unsigned sv = sptr(VsB + (buf ^ 1) * 64 * 72);
            const float* Kn = Kg + (size_t)(t + 1) * 64 * 64;
            const float* Vn = Vg + (size_t)(t + 1) * 64 * 64;
#pragma unroll
            for (int j = 0; j < 4; j++) {
                const int row = srow + j * 16;
                cpa16(sk + (row * 68 + sc4) * 4, &Kn[(size_t)row * 64 + sc4]);
                cpa16(sv + (row * 72 + sc4) * 4, &Vn[(size_t)row * 64 + sc4]);
            }
            CP_COMMIT();
        }
        const float* Ks = KsB + buf * 64 * 68;
        const float* Vs = VsB + buf * 64 * 72;

        // scores accumulator init = gene bias (fp16 LDG under GEMM1)
        float s[8][4];
        {
            const __half* brow0 = Bg + (size_t)(16 * w + g) * 2048 + t * 64;
            const __half* brow1 = brow0 + 8 * 2048;
#pragma unroll
            for (int nb = 0; nb < 8; nb++) {
                float2 lo = __half22float2(*(const __half2*)&brow0[nb * 8 + 2 * c]);
                float2 hi = __half22float2(*(const __half2*)&brow1[nb * 8 + 2 * c]);
                s[nb][0] = lo.x; s[nb][1] = lo.y;
                s[nb][2] = hi.x; s[nb][3] = hi.y;
            }
        }

        // ---- GEMM1: S = bias + (Q/8) K^T ----
#pragma unroll
        for (int kb = 0; kb < 8; kb++) {
#pragma unroll
            for (int nb = 0; nb < 8; nb++) {
                const int kr = nb * 8 + g;
                const unsigned b0 = uof(Ks[kr * 68 + kb * 8 + c]);
                const unsigned b1 = uof(Ks[kr * 68 + kb * 8 + c + 4]);
                mma8(s[nb], qA[kb], b0, b1);
            }
        }

        // ---- online softmax ----
        float mx0 = -1e30f, mx1 = -1e30f;
#pragma unroll
        for (int nb = 0; nb < 8; nb++) {
            mx0 = fmaxf(mx0, fmaxf(s[nb][0], s[nb][1]));
            mx1 = fmaxf(mx1, fmaxf(s[nb][2], s[nb][3]));
        }
        mx0 = fmaxf(mx0, __shfl_xor_sync(0xffffffffu, mx0, 1));
        mx0 = fmaxf(mx0, __shfl_xor_sync(0xffffffffu, mx0, 2));
        mx1 = fmaxf(mx1, __shfl_xor_sync(0xffffffffu, mx1, 1));
        mx1 = fmaxf(mx1, __shfl_xor_sync(0xffffffffu, mx1, 2));
        const float mn0 = fmaxf(m0, mx0), mn1 = fmaxf(m1, mx1);
        const float corr0 = __expf(m0 - mn0), corr1 = __expf(m1 - mn1);
        m0 = mn0; m1 = mn1;
        float sum0 = 0.f, sum1 = 0.f;
#pragma unroll
        for (int nb = 0; nb < 8; nb++) {
            s[nb][0] = __expf(s[nb][0] - mn0);
            s[nb][1] = __expf(s[nb][1] - mn0);
            s[nb][2] = __expf(s[nb][2] - mn1);
            s[nb][3] = __expf(s[nb][3] - mn1);
            sum0 += s[nb][0] + s[nb][1];
            sum1 += s[nb][2] + s[nb][3];
        }
        sum0 += __shfl_xor_sync(0xffffffffu, sum0, 1);
        sum0 += __shfl_xor_sync(0xffffffffu, sum0, 2);
        sum1 += __shfl_xor_sync(0xffffffffu, sum1, 1);
        sum1 += __shfl_xor_sync(0xffffffffu, sum1, 2);
        l0 = l0 * corr0 + sum0;
        l1 = l1 * corr1 + sum1;
#pragma unroll
        for (int nb = 0; nb < 8; nb++) {
            o[nb][0] *= corr0; o[nb][1] *= corr0;
            o[nb][2] *= corr1; o[nb][3] *= corr1;
        }

        // ---- GEMM2: O += P V (shfl transpose D-frag -> A-frag) ----
#pragma unroll
        for (int kb = 0; kb < 8; kb++) {
            const int s0l = base | (c >> 1);
            const int s1l = s0l + 2;
            const float p0 = s[kb][0], p1 = s[kb][1], p2 = s[kb][2], p3 = s[kb][3];
            const float x0 = __shfl_sync(0xffffffffu, p0, s0l);
            const float x1 = __shfl_sync(0xffffffffu, p1, s0l);
            const float x2 = __shfl_sync(0xffffffffu, p0, s1l);
            const float x3 = __shfl_sync(0xffffffffu, p1, s1l);
            const float y0 = __shfl_sync(0xffffffffu, p2, s0l);
            const float y1 = __shfl_sync(0xffffffffu, p3, s0l);
            const float y2 = __shfl_sync(0xffffffffu, p2, s1l);
            const float y3 = __shfl_sync(0xffffffffu, p3, s1l);
            unsigned pa[4];
            pa[0] = tf32_of((c & 1) ? x1 : x0);
            pa[2] = tf32_of((c & 1) ? x3 : x2);
            pa[1] = tf32_of((c & 1) ? y1 : y0);
            pa[3] = tf32_of((c & 1) ? y3 : y2);
#pragma unroll
            for (int nb = 0; nb < 8; nb++) {
                const unsigned b0 = uof(Vs[(kb * 8 + c) * 72 + nb * 8 + g]);
                const unsigned b1 = uof(Vs[(kb * 8 + c + 4) * 72 + nb * 8 + g]);
                mma8(o[nb], pa, b0, b1);
            }
        }
    }

    // epilogue: write tf32-rounded ctx [B][S][H*64+d]
    const float inv0 = 1.f / l0, inv1 = 1.f / l1;
    const int row0 = b * 2048 + qt * 128 + 16 * w + g;
#pragma unroll
    for (int nb = 0; nb < 8; nb++) {
        const int d = h * 64 + nb * 8 + 2 * c;
        *(float2*)&g_ctx[(size_t)row0 * 512 + d] =
            make_float2(tf32f(o[nb][0] * inv0), tf32f(o[nb][1] * inv0));
        *(float2*)&g_ctx[(size_t)(row0 + 8) * 512 + d] =
            make_float2(tf32f(o[nb][2] * inv1), tf32f(o[nb][3] * inv1));
    }
}

// ============================================================
// Kernel 4: output projection (tf32 mma, cp.async 2-stage, BK=16).
// ============================================================
__global__ __launch_bounds__(256) void out_gemm_kernel(
    const float* __restrict__ ob, float* __restrict__ C)
{
    __shared__ __align__(16) float As[2][128 * 20];
    __shared__ __align__(16) float Bs[2][128 * 20];
    const float* __restrict__ A = g_ctx;
    const float* __restrict__ W = g_wor;
    const int bm = blockIdx.y * 128;
    const int bn = blockIdx.x * 128;
    const int tid = threadIdx.x;
    const int w = tid >> 5, lane = tid & 31;
    const int g = lane >> 2, c = lane & 3;
    const int wm = (w >> 2) * 64, wn = (w & 3) * 32;

    const int srow0 = tid >> 2, sc4_0 = (tid & 3) * 4;
    const int srow1 = (tid + 256) >> 2, sc4_1 = sc4_0;

    float acc[4][4][4];
#pragma unroll
    for (int nb = 0; nb < 4; nb++) {
        const int n = bn + wn + nb * 8 + 2 * c;
        const float b0 = ob[n], b1 = ob[n + 1];
#pragma unroll
        for (int mb = 0; mb < 4; mb++) {
            acc[mb][nb][0] = b0; acc[mb][nb][1] = b1;
            acc[mb][nb][2] = b0; acc[mb][nb][3] = b1;
        }
    }

    {
        unsigned sa = sptr(&As[0][0]), sb = sptr(&Bs[0][0]);
        cpa16(sa + (srow0 * 20 + sc4_0) * 4, &A[(size_t)(bm + srow0) * 512 + sc4_0]);
        cpa16(sa + (srow1 * 20 + sc4_1) * 4, &A[(size_t)(bm + srow1) * 512 + sc4_1]);
        cpa16(sb + (srow0 * 20 + sc4_0) * 4, &W[(size_t)(bn + srow0) * 512 + sc4_0]);
        cpa16(sb + (srow1 * 20 + sc4_1) * 4, &W[(size_t)(bn + srow1) * 512 + sc4_1]);
        CP_COMMIT();
    }

    for (int t = 0; t < 32; t++) {
        CP_WAIT0();
        __syncthreads();
        const int buf = t & 1;
        if (t + 1 < 32) {
            const int kt = (t + 1) * 16;
            unsigned sa = sptr(&As[buf ^ 1][0]), sb = sptr(&Bs[buf ^ 1][0]);
            cpa16(sa + (srow0 * 20 + sc4_0) * 4, &A[(size_t)(bm + srow0) * 512 + kt + sc4_0]);
            cpa16(sa + (srow1 * 20 + sc4_1) * 4, &A[(size_t)(bm + srow1) * 512 + kt + sc4_1]);
            cpa16(sb + (srow0 * 20 + sc4_0) * 4, &W[(size_t)(bn + srow0) * 512 + kt + sc4_0]);
            cpa16(sb + (srow1 * 20 + sc4_1) * 4, &W[(size_t)(bn + srow1) * 512 + kt + sc4_1]);
            CP_COMMIT();
        }
        const float* as = As[buf];
        const float* bs = Bs[buf];
#pragma unroll
        for (int ks = 0; ks < 2; ks++) {
            unsigned a[4][4];
#pragma unroll
            for (int mb = 0; mb < 4; mb++) {
                const int r = wm + mb * 16 + g;
                a[mb][0] = uof(as[r * 20 + ks * 8 + c]);
                a[mb][1] = uof(as[(r + 8) * 20 + ks * 8 + c]);
                a[mb][2] = uof(as[r * 20 + ks * 8 + c + 4]);
                a[mb][3] = uof(as[(r + 8) * 20 + ks * 8 + c + 4]);
            }
#pragma unroll
            for (int nb = 0; nb < 4; nb++) {
                const int nr = wn + nb * 8 + g;
                const unsigned b0 = uof(bs[nr * 20 + ks * 8 + c]);
                const unsigned b1 = uof(bs[nr * 20 + ks * 8 + c + 4]);
#pragma unroll
                for (int mb = 0; mb < 4; mb++) mma8(acc[mb][nb], a[mb], b0, b1);
            }
        }
    }

#pragma unroll
    for (int mb = 0; mb < 4; mb++) {
        const int m0 = bm + wm + mb * 16 + g;
#pragma unroll
        for (int nb = 0; nb < 4; nb++) {
            const int n = bn + wn + nb * 8 + 2 * c;
            *(float2*)&C[(size_t)m0 * 512 + n] =
                make_float2(acc[mb][nb][0], acc[mb][nb][1]);
            *(float2*)&C[(size_t)(m0 + 8) * 512 + n] =
                make_float2(acc[mb][nb][2], acc[mb][nb][3]);
        }
    }
}

// ============================================================
extern "C" void kernel_launch(void* const* d_in, const int* in_sizes, int n_in,
                              void* d_out, int out_size)
{
    const float* query = (const float*)d_in[0];
    const int*   gidx  = (const int*)d_in[1];
    const float* ipw   = (const float*)d_in[2];
    const float* ipb   = (const float*)d_in[3];
    const float* outw  = (const float*)d_in[4];
    const float* outb  = (const float*)d_in[5];
    const float* gbias = (const float*)d_in[6];
    float* out = (float*)d_out;

    float *p_qr, *p_wr, *p_wor;
    cudaGetSymbolAddress((void**)&p_qr, g_qr);
    cudaGetSymbolAddress((void**)&p_wr, g_wr);
    cudaGetSymbolAddress((void**)&p_wor, g_wor);

    preround_kernel<<<2048, 256>>>((const float4*)query, (float4*)p_qr, B_ * S_ * DM_ / 4);
    preround_kernel<<<768, 256>>>((const float4*)ipw, (float4*)p_wr, 3 * DM_ * DM_ / 4);
    preround_kernel<<<256, 256>>>((const float4*)outw, (float4*)p_wor, DM_ * DM_ / 4);

    cudaFuncSetAttribute(attn_kernel, cudaFuncAttributeMaxDynamicSharedMemorySize, 71680);

    qkv_gemm_kernel<<<dim3(12, 64), 256>>>(ipb);
    bias_gather_kernel<<<dim3(128, 4), 256>>>(gidx, gbias);
    attn_kernel<<<dim3(16, 8, 4), 256, 71680>>>();
    out_gemm_kernel<<<dim3(4, 64), 256>>>(outb, out);
}

// round 5
// speedup vs baseline: 4.2864x; 1.4724x over previous
#include <cuda_runtime.h>
#include <cuda_fp16.h>

#define B_ 4
#define S_ 2048
#define H_ 8
#define DM_ 512

// ---------------- device scratch (no cudaMalloc allowed) ----------------
__device__ __half g_qh[B_ * S_ * DM_];           // query, fp16
__device__ __half g_wh[3 * DM_ * DM_];           // in_proj_weight, fp16
__device__ __half g_woh[DM_ * DM_];              // out_w, fp16
__device__ __half g_q[B_ * H_ * S_ * 64];        // [B*H][S][D], pre-scaled 1/8
__device__ __half g_k[B_ * H_ * S_ * 64];        // [B*H][S][D]
__device__ __half g_vt[B_ * H_ * 64 * S_];       // [B*H][D][S]  (transposed!)
__device__ __half g_bias[(size_t)B_ * S_ * S_];  // [B][S][S] gathered bias
__device__ __half g_ctxh[B_ * S_ * DM_];         // [B][S][DM]

// ---------------- helpers ----------------
__device__ __forceinline__ void mma16(float* d, const unsigned* a, unsigned b0, unsigned b1) {
    asm volatile(
        "mma.sync.aligned.m16n8k16.row.col.f32.f16.f16.f32 "
        "{%0,%1,%2,%3},{%4,%5,%6,%7},{%8,%9},{%0,%1,%2,%3};"
        : "+f"(d[0]), "+f"(d[1]), "+f"(d[2]), "+f"(d[3])
        : "r"(a[0]), "r"(a[1]), "r"(a[2]), "r"(a[3]), "r"(b0), "r"(b1));
}
__device__ __forceinline__ unsigned packh2(float x, float y) {
    __half2 h = __floats2half2_rn(x, y);
    return *(unsigned*)&h;
}
__device__ __forceinline__ unsigned sptr(const void* p) {
    return (unsigned)__cvta_generic_to_shared(p);
}
__device__ __forceinline__ void cpa16(unsigned s, const void* g) {
    asm volatile("cp.async.cg.shared.global [%0], [%1], 16;" :: "r"(s), "l"(g));
}
#define CP_COMMIT() asm volatile("cp.async.commit_group;")
#define CP_WAIT0()  asm volatile("cp.async.wait_group 0;")

// ============================================================
// Kernel 0: fp32 -> fp16 convert (float4 -> 4 halves)
// ============================================================
__global__ __launch_bounds__(256) void cvt_kernel(
    const float4* __restrict__ src, uint2* __restrict__ dst, int n4)
{
    for (int i = blockIdx.x * 256 + threadIdx.x; i < n4; i += gridDim.x * 256) {
        float4 v = src[i];
        dst[i] = make_uint2(packh2(v.x, v.y), packh2(v.z, v.w));
    }
}

// ============================================================
// Kernel 1: QKV projection, fp16 mma m16n8k16, cp.async 2-stage, BK=32.
// Block 128x128, 8 warps (2x4), warp 64x32.
// Q written pre-scaled 1/8 [bh][s][d]; K [bh][s][d]; V transposed [bh][d][s].
// ============================================================
__global__ __launch_bounds__(256) void qkv_gemm_kernel(const float* __restrict__ bias)
{
    __shared__ __align__(16) __half As[2][128 * 40];
    __shared__ __align__(16) __half Bs[2][128 * 40];
    const __half* __restrict__ A = g_qh;
    const __half* __restrict__ W = g_wh;
    const int bm = blockIdx.y * 128;
    const int bn = blockIdx.x * 128;
    const int tid = threadIdx.x;
    const int w = tid >> 5, lane = tid & 31;
    const int g = lane >> 2, c = lane & 3;
    const int wm = (w >> 2) * 64, wn = (w & 3) * 32;

    const int srow = tid >> 2, sh = (tid & 3) * 8;  // +256 -> row+64

    float acc[4][4][4];
#pragma unroll
    for (int nb = 0; nb < 4; nb++) {
        const int n = bn + wn + nb * 8 + 2 * c;
        const float b0 = bias[n], b1 = bias[n + 1];
#pragma unroll
        for (int mb = 0; mb < 4; mb++) {
            acc[mb][nb][0] = b0; acc[mb][nb][1] = b1;
            acc[mb][nb][2] = b0; acc[mb][nb][3] = b1;
        }
    }

    // stage tile 0
    {
        unsigned sa = sptr(&As[0][0]), sb = sptr(&Bs[0][0]);
        cpa16(sa + (srow * 40 + sh) * 2, &A[(size_t)(bm + srow) * 512 + sh]);
        cpa16(sa + ((srow + 64) * 40 + sh) * 2, &A[(size_t)(bm + srow + 64) * 512 + sh]);
        cpa16(sb + (srow * 40 + sh) * 2, &W[(size_t)(bn + srow) * 512 + sh]);
        cpa16(sb + ((srow + 64) * 40 + sh) * 2, &W[(size_t)(bn + srow + 64) * 512 + sh]);
        CP_COMMIT();
    }

    for (int t = 0; t < 16; t++) {
        CP_WAIT0();
        __syncthreads();
        const int buf = t & 1;
        if (t + 1 < 16) {
            const int kt = (t + 1) * 32;
            unsigned sa = sptr(&As[buf ^ 1][0]), sb = sptr(&Bs[buf ^ 1][0]);
            cpa16(sa + (srow * 40 + sh) * 2, &A[(size_t)(bm + srow) * 512 + kt + sh]);
            cpa16(sa + ((srow + 64) * 40 + sh) * 2, &A[(size_t)(bm + srow + 64) * 512 + kt + sh]);
            cpa16(sb + (srow * 40 + sh) * 2, &W[(size_t)(bn + srow) * 512 + kt + sh]);
            cpa16(sb + ((srow + 64) * 40 + sh) * 2, &W[(size_t)(bn + srow + 64) * 512 + kt + sh]);
            CP_COMMIT();
        }
        const __half* as = As[buf];
        const __half* bs = Bs[buf];
#pragma unroll
        for (int ks = 0; ks < 2; ks++) {
            unsigned a[4][4];
#pragma unroll
            for (int mb = 0; mb < 4; mb++) {
                const int r = wm + mb * 16 + g;
                a[mb][0] = *(const unsigned*)&as[r * 40 + ks * 16 + 2 * c];
                a[mb][1] = *(const unsigned*)&as[(r + 8) * 40 + ks * 16 + 2 * c];
                a[mb][2] = *(const unsigned*)&as[r * 40 + ks * 16 + 2 * c + 8];
                a[mb][3] = *(const unsigned*)&as[(r + 8) * 40 + ks * 16 + 2 * c + 8];
            }
#pragma unroll
            for (int nb = 0; nb < 4; nb++) {
                const int nr = wn + nb * 8 + g;
                const unsigned b0 = *(const unsigned*)&bs[nr * 40 + ks * 16 + 2 * c];
                const unsigned b1 = *(const unsigned*)&bs[nr * 40 + ks * 16 + 2 * c + 8];
#pragma unroll
                for (int mb = 0; mb < 4; mb++) mma16(acc[mb][nb], a[mb], b0, b1);
            }
        }
    }

    const int part = bn >> 9;  // 0=Q 1=K 2=V (uniform per block)
    if (part < 2) {
        __half* dst = part ? g_k : g_q;
        const float sc = part ? 1.0f : 0.125f;
#pragma unroll
        for (int mb = 0; mb < 4; mb++) {
            const int m0 = bm + wm + mb * 16 + g;
            const int bb0 = m0 >> 11, s0 = m0 & 2047;
            const int bb1 = (m0 + 8) >> 11, s1 = (m0 + 8) & 2047;
#pragma unroll
            for (int nb = 0; nb < 4; nb++) {
                const int n = bn + wn + nb * 8 + 2 * c;
                const int h = (n >> 6) & 7;
                const int d = n & 63;
                *(unsigned*)&dst[((size_t)((bb0 * 8 + h) * 2048 + s0)) * 64 + d] =
                    packh2(acc[mb][nb][0] * sc, acc[mb][nb][1] * sc);
                *(unsigned*)&dst[((size_t)((bb1 * 8 + h) * 2048 + s1)) * 64 + d] =
                    packh2(acc[mb][nb][2] * sc, acc[mb][nb][3] * sc);
            }
        }
    } else {
        // V: transposed store [bh][d][s]
#pragma unroll
        for (int mb = 0; mb < 4; mb++) {
            const int m0 = bm + wm + mb * 16 + g;
            const int bb0 = m0 >> 11, s0 = m0 & 2047;
            const int bb1 = (m0 + 8) >> 11, s1 = (m0 + 8) & 2047;
#pragma unroll
            for (int nb = 0; nb < 4; nb++) {
                const int n = bn + wn + nb * 8 + 2 * c;
                const int h = (n >> 6) & 7;
                const int d = n & 63;
                __half* p0 = &g_vt[((size_t)((bb0 * 8 + h) * 64 + d)) * 2048];
                __half* p1 = &g_vt[((size_t)((bb1 * 8 + h) * 64 + d)) * 2048];
                p0[s0] = __float2half_rn(acc[mb][nb][0]);
                p0[2048 + s0] = __float2half_rn(acc[mb][nb][1]);
                p1[s1] = __float2half_rn(acc[mb][nb][2]);
                p1[2048 + s1] = __float2half_rn(acc[mb][nb][3]);
            }
        }
    }
}

// ============================================================
// Kernel 2: gene bias gather -> fp16 table.
// ============================================================
__global__ __launch_bounds__(256) void bias_gather_kernel(
    const int* __restrict__ gi, const float* __restrict__ gb)
{
    __shared__ int cols[2048];
    const int b = blockIdx.y;
    const int qbase = blockIdx.x * 16;
    for (int i = threadIdx.x; i < 2048; i += 256) cols[i] = gi[b * 2048 + i];
    __syncthreads();
    __half* dst = g_bias + ((size_t)b * 2048 + qbase) * 2048;
    for (int q = 0; q < 16; q++) {
        const float* src = gb + (size_t)cols[qbase + q] * 8192;
        __half* drow = dst + (size_t)q * 2048;
        for (int k = threadIdx.x * 4; k < 2048; k += 1024) {
            float x0 = src[cols[k + 0]];
            float x1 = src[cols[k + 1]];
            float x2 = src[cols[k + 2]];
            float x3 = src[cols[k + 3]];
            *(uint2*)&drow[k] = make_uint2(packh2(x0, x1), packh2(x2, x3));
        }
    }
}

// ============================================================
// Kernel 3: flash attention, fp16 mma m16n8k16.
// grid (16 qtiles, 8 heads, 4 batch), 256 threads (8 warps).
// Q frags (pre-scaled) in registers; K [key][d] smem; V [d][key] smem.
// Bias fp16 as accumulator init; P D-frag -> A-frag conversion is 4 cvts.
// ============================================================
__global__ __launch_bounds__(256) void attn_kernel()
{
    __shared__ __align__(16) __half Ks[2][64 * 72];
    __shared__ __align__(16) __half Vts[2][64 * 72];

    const int qt = blockIdx.x, h = blockIdx.y, b = blockIdx.z;
    const int tid = threadIdx.x;
    const int w = tid >> 5, lane = tid & 31;
    const int g = lane >> 2, c = lane & 3;

    const size_t bh = (size_t)(b * 8 + h);
    const __half* Qg = g_q + bh * 2048 * 64;
    const __half* Kg = g_k + bh * 2048 * 64;
    const __half* Vtg = g_vt + bh * 64 * 2048;
    const __half* Bg = g_bias + ((size_t)b * 2048 + qt * 128) * 2048;

    const int srow = tid >> 3, sh = (tid & 7) * 8;  // +256 -> row+32

    // Q fragments (already scaled by 1/8 at qkv epilogue)
    unsigned qA[4][4];
    {
        const int r0 = qt * 128 + 16 * w + g;
#pragma unroll
        for (int kb = 0; kb < 4; kb++) {
            qA[kb][0] = *(const unsigned*)&Qg[(size_t)r0 * 64 + kb * 16 + 2 * c];
            qA[kb][1] = *(const unsigned*)&Qg[(size_t)(r0 + 8) * 64 + kb * 16 + 2 * c];
            qA[kb][2] = *(const unsigned*)&Qg[(size_t)r0 * 64 + kb * 16 + 2 * c + 8];
            qA[kb][3] = *(const unsigned*)&Qg[(size_t)(r0 + 8) * 64 + kb * 16 + 2 * c + 8];
        }
    }

    float o[8][4];
#pragma unroll
    for (int nb = 0; nb < 8; nb++)
#pragma unroll
        for (int i = 0; i < 4; i++) o[nb][i] = 0.f;
    float m0 = -1e30f, m1 = -1e30f, l0 = 0.f, l1 = 0.f;

    // stage tile 0
    {
        unsigned sk = sptr(&Ks[0][0]), sv = sptr(&Vts[0][0]);
        cpa16(sk + (srow * 72 + sh) * 2, &Kg[(size_t)srow * 64 + sh]);
        cpa16(sk + ((srow + 32) * 72 + sh) * 2, &Kg[(size_t)(srow + 32) * 64 + sh]);
        cpa16(sv + (srow * 72 + sh) * 2, &Vtg[(size_t)srow * 2048 + sh]);
        cpa16(sv + ((srow + 32) * 72 + sh) * 2, &Vtg[(size_t)(srow + 32) * 2048 + sh]);
        CP_COMMIT();
    }

    for (int t = 0; t < 32; t++) {
        CP_WAIT0();
        __syncthreads();
        const int buf = t & 1;
        if (t + 1 < 32) {
            unsigned sk = sptr(&Ks[buf ^ 1][0]), sv = sptr(&Vts[buf ^ 1][0]);
            const __half* Kn = Kg + (size_t)(t + 1) * 64 * 64;
            const __half* Vn = Vtg + (size_t)(t + 1) * 64;
            cpa16(sk + (srow * 72 + sh) * 2, &Kn[(size_t)srow * 64 + sh]);
            cpa16(sk + ((srow + 32) * 72 + sh) * 2, &Kn[(size_t)(srow + 32) * 64 + sh]);
            cpa16(sv + (srow * 72 + sh) * 2, &Vn[(size_t)srow * 2048 + sh]);
            cpa16(sv + ((srow + 32) * 72 + sh) * 2, &Vn[(size_t)(srow + 32) * 2048 + sh]);
            CP_COMMIT();
        }
        const __half* ks_ = Ks[buf];
        const __half* vs_ = Vts[buf];

        // scores accumulator init = gene bias
        float s[8][4];
        {
            const __half* brow0 = Bg + (size_t)(16 * w + g) * 2048 + t * 64;
            const __half* brow1 = brow0 + 8 * 2048;
#pragma unroll
            for (int nb = 0; nb < 8; nb++) {
                float2 lo = __half22float2(*(const __half2*)&brow0[nb * 8 + 2 * c]);
                float2 hi = __half22float2(*(const __half2*)&brow1[nb * 8 + 2 * c]);
                s[nb][0] = lo.x; s[nb][1] = lo.y;
                s[nb][2] = hi.x; s[nb][3] = hi.y;
            }
        }

        // ---- GEMM1: S = bias + (Q/8) K^T ----
#pragma unroll
        for (int kb = 0; kb < 4; kb++) {
#pragma unroll
            for (int nb = 0; nb < 8; nb++) {
                const int kr = nb * 8 + g;
                const unsigned b0 = *(const unsigned*)&ks_[kr * 72 + kb * 16 + 2 * c];
                const unsigned b1 = *(const unsigned*)&ks_[kr * 72 + kb * 16 + 2 * c + 8];
                mma16(s[nb], qA[kb], b0, b1);
            }
        }

        // ---- online softmax ----
        float mx0 = -1e30f, mx1 = -1e30f;
#pragma unroll
        for (int nb = 0; nb < 8; nb++) {
            mx0 = fmaxf(mx0, fmaxf(s[nb][0], s[nb][1]));
            mx1 = fmaxf(mx1, fmaxf(s[nb][2], s[nb][3]));
        }
        mx0 = fmaxf(mx0, __shfl_xor_sync(0xffffffffu, mx0, 1));
        mx0 = fmaxf(mx0, __shfl_xor_sync(0xffffffffu, mx0, 2));
        mx1 = fmaxf(mx1, __shfl_xor_sync(0xffffffffu, mx1, 1));
        mx1 = fmaxf(mx1, __shfl_xor_sync(0xffffffffu, mx1, 2));
        const float mn0 = fmaxf(m0, mx0), mn1 = fmaxf(m1, mx1);
        const float corr0 = __expf(m0 - mn0), corr1 = __expf(m1 - mn1);
        m0 = mn0; m1 = mn1;
        float sum0 = 0.f, sum1 = 0.f;
#pragma unroll
        for (int nb = 0; nb < 8; nb++) {
            s[nb][0] = __expf(s[nb][0] - mn0);
            s[nb][1] = __expf(s[nb][1] - mn0);
            s[nb][2] = __expf(s[nb][2] - mn1);
            s[nb][3] = __expf(s[nb][3] - mn1);
            sum0 += s[nb][0] + s[nb][1];
            sum1 += s[nb][2] + s[nb][3];
        }
        sum0 += __shfl_xor_sync(0xffffffffu, sum0, 1);
        sum0 += __shfl_xor_sync(0xffffffffu, sum0, 2);
        sum1 += __shfl_xor_sync(0xffffffffu, sum1, 1);
        sum1 += __shfl_xor_sync(0xffffffffu, sum1, 2);
        l0 = l0 * corr0 + sum0;
        l1 = l1 * corr1 + sum1;
#pragma unroll
        for (int nb = 0; nb < 8; nb++) {
            o[nb][0] *= corr0; o[nb][1] *= corr0;
            o[nb][2] *= corr1; o[nb][3] *= corr1;
        }

        // ---- GEMM2: O += P V.  D-frag pairs ARE the k16 A-frag. ----
#pragma unroll
        for (int kb = 0; kb < 4; kb++) {
            unsigned pa[4];
            pa[0] = packh2(s[2 * kb][0], s[2 * kb][1]);
            pa[1] = packh2(s[2 * kb][2], s[2 * kb][3]);
            pa[2] = packh2(s[2 * kb + 1][0], s[2 * kb + 1][1]);
            pa[3] = packh2(s[2 * kb + 1][2], s[2 * kb + 1][3]);
#pragma unroll
            for (int nb = 0; nb < 8; nb++) {
                const int vr = nb * 8 + g;
                const unsigned b0 = *(const unsigned*)&vs_[vr * 72 + kb * 16 + 2 * c];
                const unsigned b1 = *(const unsigned*)&vs_[vr * 72 + kb * 16 + 2 * c + 8];
                mma16(o[nb], pa, b0, b1);
            }
        }
    }

    // epilogue: write fp16 ctx [B][S][H*64+d]
    const float inv0 = 1.f / l0, inv1 = 1.f / l1;
    const int row0 = b * 2048 + qt * 128 + 16 * w + g;
#pragma unroll
    for (int nb = 0; nb < 8; nb++) {
        const int d = h * 64 + nb * 8 + 2 * c;
        *(unsigned*)&g_ctxh[(size_t)row0 * 512 + d] =
            packh2(o[nb][0] * inv0, o[nb][1] * inv0);
        *(unsigned*)&g_ctxh[(size_t)(row0 + 8) * 512 + d] =
            packh2(o[nb][2] * inv1, o[nb][3] * inv1);
    }
}

// ============================================================
// Kernel 4: output projection, fp16 mma, BK=32, 2-stage.
// ============================================================
__global__ __launch_bounds__(256) void out_gemm_kernel(
    const float* __restrict__ ob, float* __restrict__ C)
{
    __shared__ __align__(16) __half As[2][128 * 40];
    __shared__ __align__(16) __half Bs[2][128 * 40];
    const __half* __restrict__ A = g_ctxh;
    const __half* __restrict__ W = g_woh;
    const int bm = blockIdx.y * 128;
    const int bn = blockIdx.x * 128;
    const int tid = threadIdx.x;
    const int w = tid >> 5, lane = tid & 31;
    const int g = lane >> 2, c = lane & 3;
    const int wm = (w >> 2) * 64, wn = (w & 3) * 32;

    const int srow = tid >> 2, sh = (tid & 3) * 8;

    float acc[4][4][4];
#pragma unroll
    for (int nb = 0; nb < 4; nb++) {
        const int n = bn + wn + nb * 8 + 2 * c;
        const float b0 = ob[n], b1 = ob[n + 1];
#pragma unroll
        for (int mb = 0; mb < 4; mb++) {
            acc[mb][nb][0] = b0; acc[mb][nb][1] = b1;
            acc[mb][nb][2] = b0; acc[mb][nb][3] = b1;
        }
    }

    {
        unsigned sa = sptr(&As[0][0]), sb = sptr(&Bs[0][0]);
        cpa16(sa + (srow * 40 + sh) * 2, &A[(size_t)(bm + srow) * 512 + sh]);
        cpa16(sa + ((srow + 64) * 40 + sh) * 2, &A[(size_t)(bm + srow + 64) * 512 + sh]);
        cpa16(sb + (srow * 40 + sh) * 2, &W[(size_t)(bn + srow) * 512 + sh]);
        cpa16(sb + ((srow + 64) * 40 + sh) * 2, &W[(size_t)(bn + srow + 64) * 512 + sh]);
        CP_COMMIT();
    }

    for (int t = 0; t < 16; t++) {
        CP_WAIT0();
        __syncthreads();
        const int buf = t & 1;
        if (t + 1 < 16) {
            const int kt = (t + 1) * 32;
            unsigned sa = sptr(&As[buf ^ 1][0]), sb = sptr(&Bs[buf ^ 1][0]);
            cpa16(sa + (srow * 40 + sh) * 2, &A[(size_t)(bm + srow) * 512 + kt + sh]);
            cpa16(sa + ((srow + 64) * 40 + sh) * 2, &A[(size_t)(bm + srow + 64) * 512 + kt + sh]);
            cpa16(sb + (srow * 40 + sh) * 2, &W[(size_t)(bn + srow) * 512 + kt + sh]);
            cpa16(sb + ((srow + 64) * 40 + sh) * 2, &W[(size_t)(bn + srow + 64) * 512 + kt + sh]);
            CP_COMMIT();
        }
        const __half* as = As[buf];
        const __half* bs = Bs[buf];
#pragma unroll
        for (int ks = 0; ks < 2; ks++) {
            unsigned a[4][4];
#pragma unroll
            for (int mb = 0; mb < 4; mb++) {
                const int r = wm + mb * 16 + g;
                a[mb][0] = *(const unsigned*)&as[r * 40 + ks * 16 + 2 * c];
                a[mb][1] = *(const unsigned*)&as[(r + 8) * 40 + ks * 16 + 2 * c];
                a[mb][2] = *(const unsigned*)&as[r * 40 + ks * 16 + 2 * c + 8];
                a[mb][3] = *(const unsigned*)&as[(r + 8) * 40 + ks * 16 + 2 * c + 8];
            }
#pragma unroll
            for (int nb = 0; nb < 4; nb++) {
                const int nr = wn + nb * 8 + g;
                const unsigned b0 = *(const unsigned*)&bs[nr * 40 + ks * 16 + 2 * c];
                const unsigned b1 = *(const unsigned*)&bs[nr * 40 + ks * 16 + 2 * c + 8];
#pragma unroll
                for (int mb = 0; mb < 4; mb++) mma16(acc[mb][nb], a[mb], b0, b1);
            }
        }
    }

#pragma unroll
    for (int mb = 0; mb < 4; mb++) {
        const int m0 = bm + wm + mb * 16 + g;
#pragma unroll
        for (int nb = 0; nb < 4; nb++) {
            const int n = bn + wn + nb * 8 + 2 * c;
            *(float2*)&C[(size_t)m0 * 512 + n] =
                make_float2(acc[mb][nb][0], acc[mb][nb][1]);
            *(float2*)&C[(size_t)(m0 + 8) * 512 + n] =
                make_float2(acc[mb][nb][2], acc[mb][nb][3]);
        }
    }
}

// ============================================================
extern "C" void kernel_launch(void* const* d_in, const int* in_sizes, int n_in,
                              void* d_out, int out_size)
{
    const float* query = (const float*)d_in[0];
    const int*   gidx  = (const int*)d_in[1];
    const float* ipw   = (const float*)d_in[2];
    const float* ipb   = (const float*)d_in[3];
    const float* outw  = (const float*)d_in[4];
    const float* outb  = (const float*)d_in[5];
    const float* gbias = (const float*)d_in[6];
    float* out = (float*)d_out;

    void *p_qh, *p_wh, *p_woh;
    cudaGetSymbolAddress(&p_qh, g_qh);
    cudaGetSymbolAddress(&p_wh, g_wh);
    cudaGetSymbolAddress(&p_woh, g_woh);

    cvt_kernel<<<1024, 256>>>((const float4*)query, (uint2*)p_qh, B_ * S_ * DM_ / 4);
    cvt_kernel<<<384, 256>>>((const float4*)ipw, (uint2*)p_wh, 3 * DM_ * DM_ / 4);
    cvt_kernel<<<128, 256>>>((const float4*)outw, (uint2*)p_woh, DM_ * DM_ / 4);

    qkv_gemm_kernel<<<dim3(12, 64), 256>>>(ipb);
    bias_gather_kernel<<<dim3(128, 4), 256>>>(gidx, gbias);
    attn_kernel<<<dim3(16, 8, 4), 256>>>();
    out_gemm_kernel<<<dim3(4, 64), 256>>>(outb, out);
}

// round 6
// speedup vs baseline: 4.8348x; 1.1279x over previous
#include <cuda_runtime.h>
#include <cuda_fp16.h>

#define B_ 4
#define S_ 2048
#define H_ 8
#define DM_ 512

// ---------------- device scratch (no cudaMalloc allowed) ----------------
__device__ __half g_qh[B_ * S_ * DM_];           // query, fp16
__device__ __half g_wh[3 * DM_ * DM_];           // in_proj_weight, fp16
__device__ __half g_woh[DM_ * DM_];              // out_w, fp16
__device__ __half g_q[B_ * H_ * S_ * 64];        // [B*H][S][D], pre-scaled 1/8
__device__ __half g_k[B_ * H_ * S_ * 64];        // [B*H][S][D]
__device__ __half g_vt[B_ * H_ * 64 * S_];       // [B*H][D][S]  (transposed)
__device__ __half g_bias[(size_t)B_ * S_ * S_];  // [B][S][S] gathered bias
__device__ __half g_ctxh[B_ * S_ * DM_];         // [B][S][DM]

// ---------------- helpers ----------------
__device__ __forceinline__ void mma16(float* d, const unsigned* a, unsigned b0, unsigned b1) {
    asm volatile(
        "mma.sync.aligned.m16n8k16.row.col.f32.f16.f16.f32 "
        "{%0,%1,%2,%3},{%4,%5,%6,%7},{%8,%9},{%0,%1,%2,%3};"
        : "+f"(d[0]), "+f"(d[1]), "+f"(d[2]), "+f"(d[3])
        : "r"(a[0]), "r"(a[1]), "r"(a[2]), "r"(a[3]), "r"(b0), "r"(b1));
}
__device__ __forceinline__ void ldsm4(unsigned& r0, unsigned& r1, unsigned& r2, unsigned& r3,
                                      unsigned a) {
    asm volatile("ldmatrix.sync.aligned.m8n8.x4.shared.b16 {%0,%1,%2,%3}, [%4];"
                 : "=r"(r0), "=r"(r1), "=r"(r2), "=r"(r3) : "r"(a));
}
__device__ __forceinline__ unsigned packh2(float x, float y) {
    __half2 h = __floats2half2_rn(x, y);
    return *(unsigned*)&h;
}
__device__ __forceinline__ unsigned sptr(const void* p) {
    return (unsigned)__cvta_generic_to_shared(p);
}
__device__ __forceinline__ void cpa16(unsigned s, const void* g) {
    asm volatile("cp.async.cg.shared.global [%0], [%1], 16;" :: "r"(s), "l"(g));
}
#define CP_COMMIT() asm volatile("cp.async.commit_group;")
#define CP_WAIT0()  asm volatile("cp.async.wait_group 0;")

// ============================================================
// Kernel 0: fp32 -> fp16 convert
// ============================================================
__global__ __launch_bounds__(256) void cvt_kernel(
    const float4* __restrict__ src, uint2* __restrict__ dst, int n4)
{
    for (int i = blockIdx.x * 256 + threadIdx.x; i < n4; i += gridDim.x * 256) {
        float4 v = src[i];
        dst[i] = make_uint2(packh2(v.x, v.y), packh2(v.z, v.w));
    }
}

// ============================================================
// Kernel 1: QKV projection, fp16 mma + ldmatrix, cp.async 2-stage, BK=32.
// Block 128x128, 8 warps (2x4), warp 64x32.
// ============================================================
__global__ __launch_bounds__(256) void qkv_gemm_kernel(const float* __restrict__ bias)
{
    __shared__ __align__(16) __half As[2][128 * 40];
    __shared__ __align__(16) __half Bs[2][128 * 40];
    const __half* __restrict__ A = g_qh;
    const __half* __restrict__ W = g_wh;
    const int bm = blockIdx.y * 128;
    const int bn = blockIdx.x * 128;
    const int tid = threadIdx.x;
    const int w = tid >> 5, lane = tid & 31;
    const int g = lane >> 2, c = lane & 3;
    const int wm = (w >> 2) * 64, wn = (w & 3) * 32;

    const int srow = tid >> 2, sh = (tid & 3) * 8;

    // ldmatrix lane-address components
    const int arow = wm + (lane & 15);              // A: rows, +((lane>>4)<<3) col half
    const int acol8 = (lane >> 4) << 3;
    const int brow = wn + ((lane >> 4) << 3) + (lane & 7);  // B: two n-blocks per x4
    const int bcol8 = ((lane >> 3) & 1) << 3;

    float acc[4][4][4];
#pragma unroll
    for (int nb = 0; nb < 4; nb++) {
        const int n = bn + wn + nb * 8 + 2 * c;
        const float b0 = bias[n], b1 = bias[n + 1];
#pragma unroll
        for (int mb = 0; mb < 4; mb++) {
            acc[mb][nb][0] = b0; acc[mb][nb][1] = b1;
            acc[mb][nb][2] = b0; acc[mb][nb][3] = b1;
        }
    }

    {
        unsigned sa = sptr(&As[0][0]), sb = sptr(&Bs[0][0]);
        cpa16(sa + (srow * 40 + sh) * 2, &A[(size_t)(bm + srow) * 512 + sh]);
        cpa16(sa + ((srow + 64) * 40 + sh) * 2, &A[(size_t)(bm + srow + 64) * 512 + sh]);
        cpa16(sb + (srow * 40 + sh) * 2, &W[(size_t)(bn + srow) * 512 + sh]);
        cpa16(sb + ((srow + 64) * 40 + sh) * 2, &W[(size_t)(bn + srow + 64) * 512 + sh]);
        CP_COMMIT();
    }

    for (int t = 0; t < 16; t++) {
        CP_WAIT0();
        __syncthreads();
        const int buf = t & 1;
        if (t + 1 < 16) {
            const int kt = (t + 1) * 32;
            unsigned sa = sptr(&As[buf ^ 1][0]), sb = sptr(&Bs[buf ^ 1][0]);
            cpa16(sa + (srow * 40 + sh) * 2, &A[(size_t)(bm + srow) * 512 + kt + sh]);
            cpa16(sa + ((srow + 64) * 40 + sh) * 2, &A[(size_t)(bm + srow + 64) * 512 + kt + sh]);
            cpa16(sb + (srow * 40 + sh) * 2, &W[(size_t)(bn + srow) * 512 + kt + sh]);
            cpa16(sb + ((srow + 64) * 40 + sh) * 2, &W[(size_t)(bn + srow + 64) * 512 + kt + sh]);
            CP_COMMIT();
        }
        const __half* as = As[buf];
        const __half* bs = Bs[buf];
#pragma unroll
        for (int ks = 0; ks < 2; ks++) {
            unsigned a[4][4];
#pragma unroll
            for (int mb = 0; mb < 4; mb++)
                ldsm4(a[mb][0], a[mb][1], a[mb][2], a[mb][3],
                      sptr(&as[(arow + mb * 16) * 40 + ks * 16 + acol8]));
            unsigned bb[4][2];
#pragma unroll
            for (int p = 0; p < 2; p++)
                ldsm4(bb[2 * p][0], bb[2 * p][1], bb[2 * p + 1][0], bb[2 * p + 1][1],
                      sptr(&bs[(brow + p * 16) * 40 + ks * 16 + bcol8]));
#pragma unroll
            for (int nb = 0; nb < 4; nb++)
#pragma unroll
                for (int mb = 0; mb < 4; mb++)
                    mma16(acc[mb][nb], a[mb], bb[nb][0], bb[nb][1]);
        }
    }

    const int part = bn >> 9;  // 0=Q 1=K 2=V (uniform per block)
    if (part < 2) {
        __half* dst = part ? g_k : g_q;
        const float sc = part ? 1.0f : 0.125f;
#pragma unroll
        for (int mb = 0; mb < 4; mb++) {
            const int m0 = bm + wm + mb * 16 + g;
            const int bb0 = m0 >> 11, s0 = m0 & 2047;
            const int bb1 = (m0 + 8) >> 11, s1 = (m0 + 8) & 2047;
#pragma unroll
            for (int nb = 0; nb < 4; nb++) {
                const int n = bn + wn + nb * 8 + 2 * c;
                const int h = (n >> 6) & 7;
                const int d = n & 63;
                *(unsigned*)&dst[((size_t)((bb0 * 8 + h) * 2048 + s0)) * 64 + d] =
                    packh2(acc[mb][nb][0] * sc, acc[mb][nb][1] * sc);
                *(unsigned*)&dst[((size_t)((bb1 * 8 + h) * 2048 + s1)) * 64 + d] =
                    packh2(acc[mb][nb][2] * sc, acc[mb][nb][3] * sc);
            }
        }
    } else {
#pragma unroll
        for (int mb = 0; mb < 4; mb++) {
            const int m0 = bm + wm + mb * 16 + g;
            const int bb0 = m0 >> 11, s0 = m0 & 2047;
            const int bb1 = (m0 + 8) >> 11, s1 = (m0 + 8) & 2047;
#pragma unroll
            for (int nb = 0; nb < 4; nb++) {
                const int n = bn + wn + nb * 8 + 2 * c;
                const int h = (n >> 6) & 7;
                const int d = n & 63;
                __half* p0 = &g_vt[((size_t)((bb0 * 8 + h) * 64 + d)) * 2048];
                __half* p1 = &g_vt[((size_t)((bb1 * 8 + h) * 64 + d)) * 2048];
                p0[s0] = __float2half_rn(acc[mb][nb][0]);
                p0[2048 + s0] = __float2half_rn(acc[mb][nb][1]);
                p1[s1] = __float2half_rn(acc[mb][nb][2]);
                p1[2048 + s1] = __float2half_rn(acc[mb][nb][3]);
            }
        }
    }
}

// ============================================================
// Kernel 2: gene bias gather -> fp16 (8 q-rows/block for more MLP)
// ============================================================
__global__ __launch_bounds__(256) void bias_gather_kernel(
    const int* __restrict__ gi, const float* __restrict__ gb)
{
    __shared__ int cols[2048];
    const int b = blockIdx.y;
    const int qbase = blockIdx.x * 8;
    for (int i = threadIdx.x; i < 2048; i += 256) cols[i] = gi[b * 2048 + i];
    __syncthreads();
    __half* dst = g_bias + ((size_t)b * 2048 + qbase) * 2048;
    for (int q = 0; q < 8; q++) {
        const float* src = gb + (size_t)cols[qbase + q] * 8192;
        __half* drow = dst + (size_t)q * 2048;
        for (int k = threadIdx.x * 4; k < 2048; k += 1024) {
            float x0 = src[cols[k + 0]];
            float x1 = src[cols[k + 1]];
            float x2 = src[cols[k + 2]];
            float x3 = src[cols[k + 3]];
            *(uint2*)&drow[k] = make_uint2(packh2(x0, x1), packh2(x2, x3));
        }
    }
}

// ============================================================
// Kernel 3: flash attention, fp16 mma + ldmatrix.
// grid (16 qtiles, 8 heads, 4 batch), 256 threads (8 warps).
// ============================================================
__global__ __launch_bounds__(256) void attn_kernel()
{
    __shared__ __align__(16) __half Ks[2][64 * 72];
    __shared__ __align__(16) __half Vts[2][64 * 72];

    const int qt = blockIdx.x, h = blockIdx.y, b = blockIdx.z;
    const int tid = threadIdx.x;
    const int w = tid >> 5, lane = tid & 31;
    const int g = lane >> 2, c = lane & 3;

    const size_t bh = (size_t)(b * 8 + h);
    const __half* Qg = g_q + bh * 2048 * 64;
    const __half* Kg = g_k + bh * 2048 * 64;
    const __half* Vtg = g_vt + bh * 64 * 2048;
    const __half* Bg = g_bias + ((size_t)b * 2048 + qt * 128) * 2048;

    const int srow = tid >> 3, sh = (tid & 7) * 8;
    // ldmatrix B-operand lane addressing (two 8-row n-blocks per x4)
    const int lrow = ((lane >> 4) << 3) + (lane & 7);
    const int lcol8 = ((lane >> 3) & 1) << 3;

    unsigned qA[4][4];
    {
        const int r0 = qt * 128 + 16 * w + g;
#pragma unroll
        for (int kb = 0; kb < 4; kb++) {
            qA[kb][0] = *(const unsigned*)&Qg[(size_t)r0 * 64 + kb * 16 + 2 * c];
            qA[kb][1] = *(const unsigned*)&Qg[(size_t)(r0 + 8) * 64 + kb * 16 + 2 * c];
            qA[kb][2] = *(const unsigned*)&Qg[(size_t)r0 * 64 + kb * 16 + 2 * c + 8];
            qA[kb][3] = *(const unsigned*)&Qg[(size_t)(r0 + 8) * 64 + kb * 16 + 2 * c + 8];
        }
    }

    float o[8][4];
#pragma unroll
    for (int nb = 0; nb < 8; nb++)
#pragma unroll
        for (int i = 0; i < 4; i++) o[nb][i] = 0.f;
    float m0 = -1e30f, m1 = -1e30f, l0 = 0.f, l1 = 0.f;

    {
        unsigned sk = sptr(&Ks[0][0]), sv = sptr(&Vts[0][0]);
        cpa16(sk + (srow * 72 + sh) * 2, &Kg[(size_t)srow * 64 + sh]);
        cpa16(sk + ((srow + 32) * 72 + sh) * 2, &Kg[(size_t)(srow + 32) * 64 + sh]);
        cpa16(sv + (srow * 72 + sh) * 2, &Vtg[(size_t)srow * 2048 + sh]);
        cpa16(sv + ((srow + 32) * 72 + sh) * 2, &Vtg[(size_t)(srow + 32) * 2048 + sh]);
        CP_COMMIT();
    }

    for (int t = 0; t < 32; t++) {
        CP_WAIT0();
        __syncthreads();
        const int buf = t & 1;
        if (t + 1 < 32) {
            unsigned sk = sptr(&Ks[buf ^ 1][0]), sv = sptr(&Vts[buf ^ 1][0]);
            const __half* Kn = Kg + (size_t)(t + 1) * 64 * 64;
            const __half* Vn = Vtg + (size_t)(t + 1) * 64;
            cpa16(sk + (srow * 72 + sh) * 2, &Kn[(size_t)srow * 64 + sh]);
            cpa16(sk + ((srow + 32) * 72 + sh) * 2, &Kn[(size_t)(srow + 32) * 64 + sh]);
            cpa16(sv + (srow * 72 + sh) * 2, &Vn[(size_t)srow * 2048 + sh]);
            cpa16(sv + ((srow + 32) * 72 + sh) * 2, &Vn[(size_t)(srow + 32) * 2048 + sh]);
            CP_COMMIT();
        }
        const __half* ks_ = Ks[buf];
        const __half* vs_ = Vts[buf];

        // scores init = gene bias
        float s[8][4];
        {
            const __half* brow0 = Bg + (size_t)(16 * w + g) * 2048 + t * 64;
            const __half* brow1 = brow0 + 8 * 2048;
#pragma unroll
            for (int nb = 0; nb < 8; nb++) {
                float2 lo = __half22float2(*(const __half2*)&brow0[nb * 8 + 2 * c]);
                float2 hi = __half22float2(*(const __half2*)&brow1[nb * 8 + 2 * c]);
                s[nb][0] = lo.x; s[nb][1] = lo.y;
                s[nb][2] = hi.x; s[nb][3] = hi.y;
            }
        }

        // ---- GEMM1: S = bias + (Q/8) K^T ----
#pragma unroll
        for (int kb = 0; kb < 4; kb++) {
#pragma unroll
            for (int j = 0; j < 4; j++) {
                unsigned b00, b01, b10, b11;
                ldsm4(b00, b01, b10, b11,
                      sptr(&ks_[(j * 16 + lrow) * 72 + kb * 16 + lcol8]));
                mma16(s[2 * j], qA[kb], b00, b01);
                mma16(s[2 * j + 1], qA[kb], b10, b11);
            }
        }

        // ---- online softmax ----
        float mx0 = -1e30f, mx1 = -1e30f;
#pragma unroll
        for (int nb = 0; nb < 8; nb++) {
            mx0 = fmaxf(mx0, fmaxf(s[nb][0], s[nb][1]));
            mx1 = fmaxf(mx1, fmaxf(s[nb][2], s[nb][3]));
        }
        mx0 = fmaxf(mx0, __shfl_xor_sync(0xffffffffu, mx0, 1));
        mx0 = fmaxf(mx0, __shfl_xor_sync(0xffffffffu, mx0, 2));
        mx1 = fmaxf(mx1, __shfl_xor_sync(0xffffffffu, mx1, 1));
        mx1 = fmaxf(mx1, __shfl_xor_sync(0xffffffffu, mx1, 2));
        const float mn0 = fmaxf(m0, mx0), mn1 = fmaxf(m1, mx1);
        const float corr0 = __expf(m0 - mn0), corr1 = __expf(m1 - mn1);
        m0 = mn0; m1 = mn1;
        float sum0 = 0.f, sum1 = 0.f;
#pragma unroll
        for (int nb = 0; nb < 8; nb++) {
            s[nb][0] = __expf(s[nb][0] - mn0);
            s[nb][1] = __expf(s[nb][1] - mn0);
            s[nb][2] = __expf(s[nb][2] - mn1);
            s[nb][3] = __expf(s[nb][3] - mn1);
            sum0 += s[nb][0] + s[nb][1];
            sum1 += s[nb][2] + s[nb][3];
        }
        sum0 += __shfl_xor_sync(0xffffffffu, sum0, 1);
        sum0 += __shfl_xor_sync(0xffffffffu, sum0, 2);
        sum1 += __shfl_xor_sync(0xffffffffu, sum1, 1);
        sum1 += __shfl_xor_sync(0xffffffffu, sum1, 2);
        l0 = l0 * corr0 + sum0;
        l1 = l1 * corr1 + sum1;
#pragma unroll
        for (int nb = 0; nb < 8; nb++) {
            o[nb][0] *= corr0; o[nb][1] *= corr0;
            o[nb][2] *= corr1; o[nb][3] *= corr1;
        }

        // ---- GEMM2: O += P V ----
        unsigned pa[4][4];
#pragma unroll
        for (int kb = 0; kb < 4; kb++) {
            pa[kb][0] = packh2(s[2 * kb][0], s[2 * kb][1]);
            pa[kb][1] = packh2(s[2 * kb][2], s[2 * kb][3]);
            pa[kb][2] = packh2(s[2 * kb + 1][0], s[2 * kb + 1][1]);
            pa[kb][3] = packh2(s[2 * kb + 1][2], s[2 * kb + 1][3]);
        }
#pragma unroll
        for (int kb = 0; kb < 4; kb++) {
#pragma unroll
            for (int j = 0; j < 4; j++) {
                unsigned b00, b01, b10, b11;
                ldsm4(b00, b01, b10, b11,
                      sptr(&vs_[(j * 16 + lrow) * 72 + kb * 16 + lcol8]));
                mma16(o[2 * j], pa[kb], b00, b01);
                mma16(o[2 * j + 1], pa[kb], b10, b11);
            }
        }
    }

    const float inv0 = 1.f / l0, inv1 = 1.f / l1;
    const int row0 = b * 2048 + qt * 128 + 16 * w + g;
#pragma unroll
    for (int nb = 0; nb < 8; nb++) {
        const int d = h * 64 + nb * 8 + 2 * c;
        *(unsigned*)&g_ctxh[(size_t)row0 * 512 + d] =
            packh2(o[nb][0] * inv0, o[nb][1] * inv0);
        *(unsigned*)&g_ctxh[(size_t)(row0 + 8) * 512 + d] =
            packh2(o[nb][2] * inv1, o[nb][3] * inv1);
    }
}

// ============================================================
// Kernel 4: output projection, fp16 mma + ldmatrix, BK=32, 2-stage.
// ============================================================
__global__ __launch_bounds__(256) void out_gemm_kernel(
    const float* __restrict__ ob, float* __restrict__ C)
{
    __shared__ __align__(16) __half As[2][128 * 40];
    __shared__ __align__(16) __half Bs[2][128 * 40];
    const __half* __restrict__ A = g_ctxh;
    const __half* __restrict__ W = g_woh;
    const int bm = blockIdx.y * 128;
    const int bn = blockIdx.x * 128;
    const int tid = threadIdx.x;
    const int w = tid >> 5, lane = tid & 31;
    const int g = lane >> 2, c = lane & 3;
    const int wm = (w >> 2) * 64, wn = (w & 3) * 32;

    const int srow = tid >> 2, sh = (tid & 3) * 8;
    const int arow = wm + (lane & 15);
    const int acol8 = (lane >> 4) << 3;
    const int brow = wn + ((lane >> 4) << 3) + (lane & 7);
    const int bcol8 = ((lane >> 3) & 1) << 3;

    float acc[4][4][4];
#pragma unroll
    for (int nb = 0; nb < 4; nb++) {
        const int n = bn + wn + nb * 8 + 2 * c;
        const float b0 = ob[n], b1 = ob[n + 1];
#pragma unroll
        for (int mb = 0; mb < 4; mb++) {
            acc[mb][nb][0] = b0; acc[mb][nb][1] = b1;
            acc[mb][nb][2] = b0; acc[mb][nb][3] = b1;
        }
    }

    {
        unsigned sa = sptr(&As[0][0]), sb = sptr(&Bs[0][0]);
        cpa16(sa + (srow * 40 + sh) * 2, &A[(size_t)(bm + srow) * 512 + sh]);
        cpa16(sa + ((srow + 64) * 40 + sh) * 2, &A[(size_t)(bm + srow + 64) * 512 + sh]);
        cpa16(sb + (srow * 40 + sh) * 2, &W[(size_t)(bn + srow) * 512 + sh]);
        cpa16(sb + ((srow + 64) * 40 + sh) * 2, &W[(size_t)(bn + srow + 64) * 512 + sh]);
        CP_COMMIT();
    }

    for (int t = 0; t < 16; t++) {
        CP_WAIT0();
        __syncthreads();
        const int buf = t & 1;
        if (t + 1 < 16) {
            const int kt = (t + 1) * 32;
            unsigned sa = sptr(&As[buf ^ 1][0]), sb = sptr(&Bs[buf ^ 1][0]);
            cpa16(sa + (srow * 40 + sh) * 2, &A[(size_t)(bm + srow) * 512 + kt + sh]);
            cpa16(sa + ((srow + 64) * 40 + sh) * 2, &A[(size_t)(bm + srow + 64) * 512 + kt + sh]);
            cpa16(sb + (srow * 40 + sh) * 2, &W[(size_t)(bn + srow) * 512 + kt + sh]);
            cpa16(sb + ((srow + 64) * 40 + sh) * 2, &W[(size_t)(bn + srow + 64) * 512 + kt + sh]);
            CP_COMMIT();
        }
        const __half* as = As[buf];
        const __half* bs = Bs[buf];
#pragma unroll
        for (int ks = 0; ks < 2; ks++) {
            unsigned a[4][4];
#pragma unroll
            for (int mb = 0; mb < 4; mb++)
                ldsm4(a[mb][0], a[mb][1], a[mb][2], a[mb][3],
                      sptr(&as[(arow + mb * 16) * 40 + ks * 16 + acol8]));
            unsigned bb[4][2];
#pragma unroll
            for (int p = 0; p < 2; p++)
                ldsm4(bb[2 * p][0], bb[2 * p][1], bb[2 * p + 1][0], bb[2 * p + 1][1],
                      sptr(&bs[(brow + p * 16) * 40 + ks * 16 + bcol8]));
#pragma unroll
            for (int nb = 0; nb < 4; nb++)
#pragma unroll
                for (int mb = 0; mb < 4; mb++)
                    mma16(acc[mb][nb], a[mb], bb[nb][0], bb[nb][1]);
        }
    }

#pragma unroll
    for (int mb = 0; mb < 4; mb++) {
        const int m0 = bm + wm + mb * 16 + g;
#pragma unroll
        for (int nb = 0; nb < 4; nb++) {
            const int n = bn + wn + nb * 8 + 2 * c;
            *(float2*)&C[(size_t)m0 * 512 + n] =
                make_float2(acc[mb][nb][0], acc[mb][nb][1]);
            *(float2*)&C[(size_t)(m0 + 8) * 512 + n] =
                make_float2(acc[mb][nb][2], acc[mb][nb][3]);
        }
    }
}

// ============================================================
extern "C" void kernel_launch(void* const* d_in, const int* in_sizes, int n_in,
                              void* d_out, int out_size)
{
    const float* query = (const float*)d_in[0];
    const int*   gidx  = (const int*)d_in[1];
    const float* ipw   = (const float*)d_in[2];
    const float* ipb   = (const float*)d_in[3];
    const float* outw  = (const float*)d_in[4];
    const float* outb  = (const float*)d_in[5];
    const float* gbias = (const float*)d_in[6];
    float* out = (float*)d_out;

    void *p_qh, *p_wh, *p_woh;
    cudaGetSymbolAddress(&p_qh, g_qh);
    cudaGetSymbolAddress(&p_wh, g_wh);
    cudaGetSymbolAddress(&p_woh, g_woh);

    cvt_kernel<<<1024, 256>>>((const float4*)query, (uint2*)p_qh, B_ * S_ * DM_ / 4);
    cvt_kernel<<<384, 256>>>((const float4*)ipw, (uint2*)p_wh, 3 * DM_ * DM_ / 4);
    cvt_kernel<<<128, 256>>>((const float4*)outw, (uint2*)p_woh, DM_ * DM_ / 4);

    qkv_gemm_kernel<<<dim3(12, 64), 256>>>(ipb);
    bias_gather_kernel<<<dim3(256, 4), 256>>>(gidx, gbias);
    attn_kernel<<<dim3(16, 8, 4), 256>>>();
    out_gemm_kernel<<<dim3(4, 64), 256>>>(outb, out);
}

// round 7
// speedup vs baseline: 5.2046x; 1.0765x over previous
#include <cuda_runtime.h>
#include <cuda_fp16.h>

#define B_ 4
#define S_ 2048
#define H_ 8
#define DM_ 512
#define L2E 1.4426950408889634f

// ---------------- device scratch (no cudaMalloc allowed) ----------------
__device__ __half g_qh[B_ * S_ * DM_];           // query, fp16
__device__ __half g_wh[3 * DM_ * DM_];           // in_proj_weight, fp16
__device__ __half g_woh[DM_ * DM_];              // out_w, fp16
__device__ __half g_q[B_ * H_ * S_ * 64];        // [B*H][S][D], pre-scaled 0.125*log2e
__device__ __half g_k[B_ * H_ * S_ * 64];        // [B*H][S][D]
__device__ __half g_vt[B_ * H_ * 64 * S_];       // [B*H][D][S]  (transposed)
__device__ __half g_bias[(size_t)B_ * S_ * S_];  // [B][S][S] bias * log2e, fp16
__device__ __half g_ctxh[B_ * S_ * DM_];         // [B][S][DM]

// ---------------- helpers ----------------
__device__ __forceinline__ void mma16(float* d, const unsigned* a, unsigned b0, unsigned b1) {
    asm volatile(
        "mma.sync.aligned.m16n8k16.row.col.f32.f16.f16.f32 "
        "{%0,%1,%2,%3},{%4,%5,%6,%7},{%8,%9},{%0,%1,%2,%3};"
        : "+f"(d[0]), "+f"(d[1]), "+f"(d[2]), "+f"(d[3])
        : "r"(a[0]), "r"(a[1]), "r"(a[2]), "r"(a[3]), "r"(b0), "r"(b1));
}
__device__ __forceinline__ void ldsm4(unsigned& r0, unsigned& r1, unsigned& r2, unsigned& r3,
                                      unsigned a) {
    asm volatile("ldmatrix.sync.aligned.m8n8.x4.shared.b16 {%0,%1,%2,%3}, [%4];"
                 : "=r"(r0), "=r"(r1), "=r"(r2), "=r"(r3) : "r"(a));
}
__device__ __forceinline__ unsigned packh2(float x, float y) {
    __half2 h = __floats2half2_rn(x, y);
    return *(unsigned*)&h;
}
__device__ __forceinline__ unsigned sptr(const void* p) {
    return (unsigned)__cvta_generic_to_shared(p);
}
__device__ __forceinline__ void cpa16(unsigned s, const void* g) {
    asm volatile("cp.async.cg.shared.global [%0], [%1], 16;" :: "r"(s), "l"(g));
}
#define CP_COMMIT() asm volatile("cp.async.commit_group;")
#define CP_WAIT0()  asm volatile("cp.async.wait_group 0;")

// ============================================================
// Kernel 0: fused fp32 -> fp16 convert for query / in_proj_w / out_w
// ============================================================
#define NQ4 (B_ * S_ * DM_ / 4)
#define NW4 (3 * DM_ * DM_ / 4)
#define NO4 (DM_ * DM_ / 4)
__global__ __launch_bounds__(256) void cvt3_kernel(
    const float4* __restrict__ q, const float4* __restrict__ w,
    const float4* __restrict__ wo)
{
    for (int i = blockIdx.x * 256 + threadIdx.x; i < NQ4 + NW4 + NO4;
         i += gridDim.x * 256) {
        const float4* src;
        uint2* dst;
        int j = i;
        if (j < NQ4) { src = q; dst = (uint2*)g_qh; }
        else if ((j -= NQ4) < NW4) { src = w; dst = (uint2*)g_wh; }
        else { j -= NW4; src = wo; dst = (uint2*)g_woh; }
        float4 v = src[j];
        dst[j] = make_uint2(packh2(v.x, v.y), packh2(v.z, v.w));
    }
}

// ============================================================
// Kernel 1 (fused): QKV projection + gene bias gather, interleaved roles.
// 1792 blocks: id%7<3 -> qkv (768 blocks), else gather (1024 blocks).
// ============================================================
__global__ __launch_bounds__(256) void qkv_gather_kernel(
    const float* __restrict__ bias,
    const int* __restrict__ gi, const float* __restrict__ gb)
{
    __shared__ __align__(16) __half As[2][128 * 40];
    __shared__ __align__(16) __half Bs[2][128 * 40];

    const int id = blockIdx.x;
    const int grp = id / 7, rem = id % 7;

    if (rem >= 3) {
        // ---------------- gather role ----------------
        const int gid = grp * 4 + (rem - 3);  // 0..1023
        const int b = gid >> 8;
        const int qbase = (gid & 255) * 8;
        int* cols = (int*)&As[0][0];
        for (int i = threadIdx.x; i < 2048; i += 256) cols[i] = gi[b * 2048 + i];
        __syncthreads();
        __half* dst = g_bias + ((size_t)b * 2048 + qbase) * 2048;
        for (int q = 0; q < 8; q++) {
            const float* src = gb + (size_t)cols[qbase + q] * 8192;
            __half* drow = dst + (size_t)q * 2048;
            for (int k = threadIdx.x * 4; k < 2048; k += 1024) {
                float x0 = src[cols[k + 0]] * L2E;
                float x1 = src[cols[k + 1]] * L2E;
                float x2 = src[cols[k + 2]] * L2E;
                float x3 = src[cols[k + 3]] * L2E;
                *(uint2*)&drow[k] = make_uint2(packh2(x0, x1), packh2(x2, x3));
            }
        }
        return;
    }

    // ---------------- qkv role ----------------
    const int qid = grp * 3 + rem;  // 0..767
    const int bm = (qid / 12) * 128;
    const int bn = (qid % 12) * 128;
    const __half* __restrict__ A = g_qh;
    const __half* __restrict__ W = g_wh;
    const int tid = threadIdx.x;
    const int w = tid >> 5, lane = tid & 31;
    const int g = lane >> 2, c = lane & 3;
    const int wm = (w >> 2) * 64, wn = (w & 3) * 32;

    const int srow = tid >> 2, sh = (tid & 3) * 8;
    const int arow = wm + (lane & 15);
    const int acol8 = (lane >> 4) << 3;
    const int brow = wn + ((lane >> 4) << 3) + (lane & 7);
    const int bcol8 = ((lane >> 3) & 1) << 3;

    float acc[4][4][4];
#pragma unroll
    for (int nb = 0; nb < 4; nb++) {
        const int n = bn + wn + nb * 8 + 2 * c;
        const float b0 = bias[n], b1 = bias[n + 1];
#pragma unroll
        for (int mb = 0; mb < 4; mb++) {
            acc[mb][nb][0] = b0; acc[mb][nb][1] = b1;
            acc[mb][nb][2] = b0; acc[mb][nb][3] = b1;
        }
    }

    {
        unsigned sa = sptr(&As[0][0]), sb = sptr(&Bs[0][0]);
        cpa16(sa + (srow * 40 + sh) * 2, &A[(size_t)(bm + srow) * 512 + sh]);
        cpa16(sa + ((srow + 64) * 40 + sh) * 2, &A[(size_t)(bm + srow + 64) * 512 + sh]);
        cpa16(sb + (srow * 40 + sh) * 2, &W[(size_t)(bn + srow) * 512 + sh]);
        cpa16(sb + ((srow + 64) * 40 + sh) * 2, &W[(size_t)(bn + srow + 64) * 512 + sh]);
        CP_COMMIT();
    }

    for (int t = 0; t < 16; t++) {
        CP_WAIT0();
        __syncthreads();
        const int buf = t & 1;
        if (t + 1 < 16) {
            const int kt = (t + 1) * 32;
            unsigned sa = sptr(&As[buf ^ 1][0]), sb = sptr(&Bs[buf ^ 1][0]);
            cpa16(sa + (srow * 40 + sh) * 2, &A[(size_t)(bm + srow) * 512 + kt + sh]);
            cpa16(sa + ((srow + 64) * 40 + sh) * 2, &A[(size_t)(bm + srow + 64) * 512 + kt + sh]);
            cpa16(sb + (srow * 40 + sh) * 2, &W[(size_t)(bn + srow) * 512 + kt + sh]);
            cpa16(sb + ((srow + 64) * 40 + sh) * 2, &W[(size_t)(bn + srow + 64) * 512 + kt + sh]);
            CP_COMMIT();
        }
        const __half* as = As[buf];
        const __half* bs = Bs[buf];
#pragma unroll
        for (int ks = 0; ks < 2; ks++) {
            unsigned a[4][4];
#pragma unroll
            for (int mb = 0; mb < 4; mb++)
                ldsm4(a[mb][0], a[mb][1], a[mb][2], a[mb][3],
                      sptr(&as[(arow + mb * 16) * 40 + ks * 16 + acol8]));
            unsigned bb[4][2];
#pragma unroll
            for (int p = 0; p < 2; p++)
                ldsm4(bb[2 * p][0], bb[2 * p][1], bb[2 * p + 1][0], bb[2 * p + 1][1],
                      sptr(&bs[(brow + p * 16) * 40 + ks * 16 + bcol8]));
#pragma unroll
            for (int nb = 0; nb < 4; nb++)
#pragma unroll
                for (int mb = 0; mb < 4; mb++)
                    mma16(acc[mb][nb], a[mb], bb[nb][0], bb[nb][1]);
        }
    }

    const int part = bn >> 9;  // 0=Q 1=K 2=V (uniform per block)
    if (part < 2) {
        __half* dst = part ? g_k : g_q;
        const float sc = part ? 1.0f : 0.125f * L2E;  // fold softmax scale+log2e into Q
#pragma unroll
        for (int mb = 0; mb < 4; mb++) {
            const int m0 = bm + wm + mb * 16 + g;
            const int bb0 = m0 >> 11, s0 = m0 & 2047;
            const int bb1 = (m0 + 8) >> 11, s1 = (m0 + 8) & 2047;
#pragma unroll
            for (int nb = 0; nb < 4; nb++) {
                const int n = bn + wn + nb * 8 + 2 * c;
                const int h = (n >> 6) & 7;
                const int d = n & 63;
                *(unsigned*)&dst[((size_t)((bb0 * 8 + h) * 2048 + s0)) * 64 + d] =
                    packh2(acc[mb][nb][0] * sc, acc[mb][nb][1] * sc);
                *(unsigned*)&dst[((size_t)((bb1 * 8 + h) * 2048 + s1)) * 64 + d] =
                    packh2(acc[mb][nb][2] * sc, acc[mb][nb][3] * sc);
            }
        }
    } else {
#pragma unroll
        for (int mb = 0; mb < 4; mb++) {
            const int m0 = bm + wm + mb * 16 + g;
            const int bb0 = m0 >> 11, s0 = m0 & 2047;
            const int bb1 = (m0 + 8) >> 11, s1 = (m0 + 8) & 2047;
#pragma unroll
            for (int nb = 0; nb < 4; nb++) {
                const int n = bn + wn + nb * 8 + 2 * c;
                const int h = (n >> 6) & 7;
                const int d = n & 63;
                __half* p0 = &g_vt[((size_t)((bb0 * 8 + h) * 64 + d)) * 2048];
                __half* p1 = &g_vt[((size_t)((bb1 * 8 + h) * 64 + d)) * 2048];
                p0[s0] = __float2half_rn(acc[mb][nb][0]);
                p0[2048 + s0] = __float2half_rn(acc[mb][nb][1]);
                p1[s1] = __float2half_rn(acc[mb][nb][2]);
                p1[2048 + s1] = __float2half_rn(acc[mb][nb][3]);
            }
        }
    }
}

// ============================================================
// Kernel 3: flash attention, fp16 mma + ldmatrix, exp2 softmax.
// grid (16 qtiles, 8 heads, 4 batch), 256 threads (8 warps).
// ============================================================
__global__ __launch_bounds__(256) void attn_kernel()
{
    __shared__ __align__(16) __half Ks[2][64 * 72];
    __shared__ __align__(16) __half Vts[2][64 * 72];

    const int qt = blockIdx.x, h = blockIdx.y, b = blockIdx.z;
    const int tid = threadIdx.x;
    const int w = tid >> 5, lane = tid & 31;
    const int g = lane >> 2, c = lane & 3;

    const size_t bh = (size_t)(b * 8 + h);
    const __half* Qg = g_q + bh * 2048 * 64;
    const __half* Kg = g_k + bh * 2048 * 64;
    const __half* Vtg = g_vt + bh * 64 * 2048;
    const __half* Bg = g_bias + ((size_t)b * 2048 + qt * 128) * 2048;

    const int srow = tid >> 3, sh = (tid & 7) * 8;
    const int lrow = ((lane >> 4) << 3) + (lane & 7);
    const int lcol8 = ((lane >> 3) & 1) << 3;

    unsigned qA[4][4];
    {
        const int r0 = qt * 128 + 16 * w + g;
#pragma unroll
        for (int kb = 0; kb < 4; kb++) {
            qA[kb][0] = *(const unsigned*)&Qg[(size_t)r0 * 64 + kb * 16 + 2 * c];
            qA[kb][1] = *(const unsigned*)&Qg[(size_t)(r0 + 8) * 64 + kb * 16 + 2 * c];
            qA[kb][2] = *(const unsigned*)&Qg[(size_t)r0 * 64 + kb * 16 + 2 * c + 8];
            qA[kb][3] = *(const unsigned*)&Qg[(size_t)(r0 + 8) * 64 + kb * 16 + 2 * c + 8];
        }
    }

    float o[8][4];
#pragma unroll
    for (int nb = 0; nb < 8; nb++)
#pragma unroll
        for (int i = 0; i < 4; i++) o[nb][i] = 0.f;
    float m0 = -1e30f, m1 = -1e30f, l0 = 0.f, l1 = 0.f;

    {
        unsigned sk = sptr(&Ks[0][0]), sv = sptr(&Vts[0][0]);
        cpa16(sk + (srow * 72 + sh) * 2, &Kg[(size_t)srow * 64 + sh]);
        cpa16(sk + ((srow + 32) * 72 + sh) * 2, &Kg[(size_t)(srow + 32) * 64 + sh]);
        cpa16(sv + (srow * 72 + sh) * 2, &Vtg[(size_t)srow * 2048 + sh]);
        cpa16(sv + ((srow + 32) * 72 + sh) * 2, &Vtg[(size_t)(srow + 32) * 2048 + sh]);
        CP_COMMIT();
    }

    for (int t = 0; t < 32; t++) {
        CP_WAIT0();
        __syncthreads();
        const int buf = t & 1;
        if (t + 1 < 32) {
            unsigned sk = sptr(&Ks[buf ^ 1][0]), sv = sptr(&Vts[buf ^ 1][0]);
            const __half* Kn = Kg + (size_t)(t + 1) * 64 * 64;
            const __half* Vn = Vtg + (size_t)(t + 1) * 64;
            cpa16(sk + (srow * 72 + sh) * 2, &Kn[(size_t)srow * 64 + sh]);
            cpa16(sk + ((srow + 32) * 72 + sh) * 2, &Kn[(size_t)(srow + 32) * 64 + sh]);
            cpa16(sv + (srow * 72 + sh) * 2, &Vn[(size_t)srow * 2048 + sh]);
            cpa16(sv + ((srow + 32) * 72 + sh) * 2, &Vn[(size_t)(srow + 32) * 2048 + sh]);
            CP_COMMIT();
        }
        const __half* ks_ = Ks[buf];
        const __half* vs_ = Vts[buf];

        // scores init = gene bias (already * log2e)
        float s[8][4];
        {
            const __half* brow0 = Bg + (size_t)(16 * w + g) * 2048 + t * 64;
            const __half* brow1 = brow0 + 8 * 2048;
#pragma unroll
            for (int nb = 0; nb < 8; nb++) {
                float2 lo = __half22float2(*(const __half2*)&brow0[nb * 8 + 2 * c]);
                float2 hi = __half22float2(*(const __half2*)&brow1[nb * 8 + 2 * c]);
                s[nb][0] = lo.x; s[nb][1] = lo.y;
                s[nb][2] = hi.x; s[nb][3] = hi.y;
            }
        }

        // ---- GEMM1: S = bias*log2e + Q*(log2e/8) K^T ----
#pragma unroll
        for (int kb = 0; kb < 4; kb++) {
#pragma unroll
            for (int j = 0; j < 4; j++) {
                unsigned b00, b01, b10, b11;
                ldsm4(b00, b01, b10, b11,
                      sptr(&ks_[(j * 16 + lrow) * 72 + kb * 16 + lcol8]));
                mma16(s[2 * j], qA[kb], b00, b01);
                mma16(s[2 * j + 1], qA[kb], b10, b11);
            }
        }

        // ---- online softmax (base-2 domain) ----
        float mx0 = -1e30f, mx1 = -1e30f;
#pragma unroll
        for (int nb = 0; nb < 8; nb++) {
            mx0 = fmaxf(mx0, fmaxf(s[nb][0], s[nb][1]));
            mx1 = fmaxf(mx1, fmaxf(s[nb][2], s[nb][3]));
        }
        mx0 = fmaxf(mx0, __shfl_xor_sync(0xffffffffu, mx0, 1));
        mx0 = fmaxf(mx0, __shfl_xor_sync(0xffffffffu, mx0, 2));
        mx1 = fmaxf(mx1, __shfl_xor_sync(0xffffffffu, mx1, 1));
        mx1 = fmaxf(mx1, __shfl_xor_sync(0xffffffffu, mx1, 2));
        const float mn0 = fmaxf(m0, mx0), mn1 = fmaxf(m1, mx1);
        const float corr0 = exp2f(m0 - mn0), corr1 = exp2f(m1 - mn1);
        m0 = mn0; m1 = mn1;
        float sum0 = 0.f, sum1 = 0.f;
#pragma unroll
        for (int nb = 0; nb < 8; nb++) {
            s[nb][0] = exp2f(s[nb][0] - mn0);
            s[nb][1] = exp2f(s[nb][1] - mn0);
            s[nb][2] = exp2f(s[nb][2] - mn1);
            s[nb][3] = exp2f(s[nb][3] - mn1);
            sum0 += s[nb][0] + s[nb][1];
            sum1 += s[nb][2] + s[nb][3];
        }
        sum0 += __shfl_xor_sync(0xffffffffu, sum0, 1);
        sum0 += __shfl_xor_sync(0xffffffffu, sum0, 2);
        sum1 += __shfl_xor_sync(0xffffffffu, sum1, 1);
        sum1 += __shfl_xor_sync(0xffffffffu, sum1, 2);
        l0 = l0 * corr0 + sum0;
        l1 = l1 * corr1 + sum1;
#pragma unroll
        for (int nb = 0; nb < 8; nb++) {
            o[nb][0] *= corr0; o[nb][1] *= corr0;
            o[nb][2] *= corr1; o[nb][3] *= corr1;
        }

        // ---- GEMM2: O += P V ----
        unsigned pa[4][4];
#pragma unroll
        for (int kb = 0; kb < 4; kb++) {
            pa[kb][0] = packh2(s[2 * kb][0], s[2 * kb][1]);
            pa[kb][1] = packh2(s[2 * kb][2], s[2 * kb][3]);
            pa[kb][2] = packh2(s[2 * kb + 1][0], s[2 * kb + 1][1]);
            pa[kb][3] = packh2(s[2 * kb + 1][2], s[2 * kb + 1][3]);
        }
#pragma unroll
        for (int kb = 0; kb < 4; kb++) {
#pragma unroll
            for (int j = 0; j < 4; j++) {
                unsigned b00, b01, b10, b11;
                ldsm4(b00, b01, b10, b11,
                      sptr(&vs_[(j * 16 + lrow) * 72 + kb * 16 + lcol8]));
                mma16(o[2 * j], pa[kb], b00, b01);
                mma16(o[2 * j + 1], pa[kb], b10, b11);
            }
        }
    }

    const float inv0 = 1.f / l0, inv1 = 1.f / l1;
    const int row0 = b * 2048 + qt * 128 + 16 * w + g;
#pragma unroll
    for (int nb = 0; nb < 8; nb++) {
        const int d = h * 64 + nb * 8 + 2 * c;
        *(unsigned*)&g_ctxh[(size_t)row0 * 512 + d] =
            packh2(o[nb][0] * inv0, o[nb][1] * inv0);
        *(unsigned*)&g_ctxh[(size_t)(row0 + 8) * 512 + d] =
            packh2(o[nb][2] * inv1, o[nb][3] * inv1);
    }
}

// ============================================================
// Kernel 4: output projection, fp16 mma + ldmatrix, BK=32, 2-stage.
// ============================================================
__global__ __launch_bounds__(256) void out_gemm_kernel(
    const float* __restrict__ ob, float* __restrict__ C)
{
    __shared__ __align__(16) __half As[2][128 * 40];
    __shared__ __align__(16) __half Bs[2][128 * 40];
    const __half* __restrict__ A = g_ctxh;
    const __half* __restrict__ W = g_woh;
    const int bm = blockIdx.y * 128;
    const int bn = blockIdx.x * 128;
    const int tid = threadIdx.x;
    const int w = tid >> 5, lane = tid & 31;
    const int g = lane >> 2, c = lane & 3;
    const int wm = (w >> 2) * 64, wn = (w & 3) * 32;

    const int srow = tid >> 2, sh = (tid & 3) * 8;
    const int arow = wm + (lane & 15);
    const int acol8 = (lane >> 4) << 3;
    const int brow = wn + ((lane >> 4) << 3) + (lane & 7);
    const int bcol8 = ((lane >> 3) & 1) << 3;

    float acc[4][4][4];
#pragma unroll
    for (int nb = 0; nb < 4; nb++) {
        const int n = bn + wn + nb * 8 + 2 * c;
        const float b0 = ob[n], b1 = ob[n + 1];
#pragma unroll
        for (int mb = 0; mb < 4; mb++) {
            acc[mb][nb][0] = b0; acc[mb][nb][1] = b1;
            acc[mb][nb][2] = b0; acc[mb][nb][3] = b1;
        }
    }

    {
        unsigned sa = sptr(&As[0][0]), sb = sptr(&Bs[0][0]);
        cpa16(sa + (srow * 40 + sh) * 2, &A[(size_t)(bm + srow) * 512 + sh]);
        cpa16(sa + ((srow + 64) * 40 + sh) * 2, &A[(size_t)(bm + srow + 64) * 512 + sh]);
        cpa16(sb + (srow * 40 + sh) * 2, &W[(size_t)(bn + srow) * 512 + sh]);
        cpa16(sb + ((srow + 64) * 40 + sh) * 2, &W[(size_t)(bn + srow + 64) * 512 + sh]);
        CP_COMMIT();
    }

    for (int t = 0; t < 16; t++) {
        CP_WAIT0();
        __syncthreads();
        const int buf = t & 1;
        if (t + 1 < 16) {
            const int kt = (t + 1) * 32;
            unsigned sa = sptr(&As[buf ^ 1][0]), sb = sptr(&Bs[buf ^ 1][0]);
            cpa16(sa + (srow * 40 + sh) * 2, &A[(size_t)(bm + srow) * 512 + kt + sh]);
            cpa16(sa + ((srow + 64) * 40 + sh) * 2, &A[(size_t)(bm + srow + 64) * 512 + kt + sh]);
            cpa16(sb + (srow * 40 + sh) * 2, &W[(size_t)(bn + srow) * 512 + kt + sh]);
            cpa16(sb + ((srow + 64) * 40 + sh) * 2, &W[(size_t)(bn + srow + 64) * 512 + kt + sh]);
            CP_COMMIT();
        }
        const __half* as = As[buf];
        const __half* bs = Bs[buf];
#pragma unroll
        for (int ks = 0; ks < 2; ks++) {
            unsigned a[4][4];
#pragma unroll
            for (int mb = 0; mb < 4; mb++)
                ldsm4(a[mb][0], a[mb][1], a[mb][2], a[mb][3],
                      sptr(&as[(arow + mb * 16) * 40 + ks * 16 + acol8]));
            unsigned bb[4][2];
#pragma unroll
            for (int p = 0; p < 2; p++)
                ldsm4(bb[2 * p][0], bb[2 * p][1], bb[2 * p + 1][0], bb[2 * p + 1][1],
                      sptr(&bs[(brow + p * 16) * 40 + ks * 16 + bcol8]));
#pragma unroll
            for (int nb = 0; nb < 4; nb++)
#pragma unroll
                for (int mb = 0; mb < 4; mb++)
                    mma16(acc[mb][nb], a[mb], bb[nb][0], bb[nb][1]);
        }
    }

#pragma unroll
    for (int mb = 0; mb < 4; mb++) {
        const int m0 = bm + wm + mb * 16 + g;
#pragma unroll
        for (int nb = 0; nb < 4; nb++) {
            const int n = bn + wn + nb * 8 + 2 * c;
            *(float2*)&C[(size_t)m0 * 512 + n] =
                make_float2(acc[mb][nb][0], acc[mb][nb][1]);
            *(float2*)&C[(size_t)(m0 + 8) * 512 + n] =
                make_float2(acc[mb][nb][2], acc[mb][nb][3]);
        }
    }
}

// ============================================================
extern "C" void kernel_launch(void* const* d_in, const int* in_sizes, int n_in,
                              void* d_out, int out_size)
{
    const float* query = (const float*)d_in[0];
    const int*   gidx  = (const int*)d_in[1];
    const float* ipw   = (const float*)d_in[2];
    const float* ipb   = (const float*)d_in[3];
    const float* outw  = (const float*)d_in[4];
    const float* outb  = (const float*)d_in[5];
    const float* gbias = (const float*)d_in[6];
    float* out = (float*)d_out;

    cvt3_kernel<<<1280, 256>>>((const float4*)query, (const float4*)ipw,
                               (const float4*)outw);
    qkv_gather_kernel<<<1792, 256>>>(ipb, gidx, gbias);
    attn_kernel<<<dim3(16, 8, 4), 256>>>();
    out_gemm_kernel<<<dim3(4, 64), 256>>>(outb, out);
}